// round 12
// baseline (speedup 1.0000x reference)
#include <cuda_runtime.h>
#include <cuda_bf16.h>
#include <cuda_fp16.h>
#include <cstdint>

#define NN    8192
#define CC    128
#define KNBR  7
#define QUARTN 2048
#define NTQ   (QUARTN / 128)
#define NTA   (QUARTN / 64)
#define NCQ   8

typedef unsigned long long ull;

// ---------------- device scratch ----------------
__device__ float g_skip[NN * CC];
__device__ float g_h[NN * CC];
__device__ float g_acc[4 * NN * CC];
__device__ float g_l[4 * NN];
__device__ float g_norm[NN];
__device__ int   g_ci8[4 * NN * NCQ];
__device__ int   g_idx[NN * KNBR];
__device__ float g_m1[NN * CC];
__device__ float g_h1[NN * CC];
__device__ float g_m2[NN];
__device__ __nv_bfloat16 g_qb0[NN * CC], g_qb1[NN * CC];
__device__ __nv_bfloat16 g_kb0[NN * CC], g_kb1[NN * CC];
__device__ __half        g_vh[NN * CC];
__device__ __nv_bfloat16 g_hb0[NN * CC];

// ---------------- packed fp32x2 (SIMT GEMMs) ----------------
__device__ __forceinline__ ull ffma2(ull a, ull b, ull c) {
    ull d;
    asm("fma.rn.f32x2 %0, %1, %2, %3;" : "=l"(d) : "l"(a), "l"(b), "l"(c));
    return d;
}
__device__ __forceinline__ ull dup2(float x) {
    ull d;
    asm("mov.b64 %0, {%1, %1};" : "=l"(d) : "f"(x));
    return d;
}
__device__ __forceinline__ float2 upk(ull v) {
    float2 r;
    asm("mov.b64 {%0, %1}, %2;" : "=f"(r.x), "=f"(r.y) : "l"(v));
    return r;
}

// ---------------- mma / ldmatrix / cp.async helpers ----------------
__device__ __forceinline__ uint32_t smem_u32(const void* p) {
    uint32_t a;
    asm("{ .reg .u64 t; cvta.to.shared.u64 t, %1; cvt.u32.u64 %0, t; }" : "=r"(a) : "l"(p));
    return a;
}
__device__ __forceinline__ void ldsm4(uint32_t* r, uint32_t a) {
    asm volatile("ldmatrix.sync.aligned.m8n8.x4.shared.b16 {%0,%1,%2,%3}, [%4];"
                 : "=r"(r[0]), "=r"(r[1]), "=r"(r[2]), "=r"(r[3]) : "r"(a));
}
__device__ __forceinline__ void ldsm4t(uint32_t* r, uint32_t a) {
    asm volatile("ldmatrix.sync.aligned.m8n8.x4.trans.shared.b16 {%0,%1,%2,%3}, [%4];"
                 : "=r"(r[0]), "=r"(r[1]), "=r"(r[2]), "=r"(r[3]) : "r"(a));
}
__device__ __forceinline__ void mma16816(float* c, const uint32_t* a, uint32_t b0, uint32_t b1) {
    asm volatile(
        "mma.sync.aligned.m16n8k16.row.col.f32.bf16.bf16.f32 "
        "{%0,%1,%2,%3}, {%4,%5,%6,%7}, {%8,%9}, {%0,%1,%2,%3};"
        : "+f"(c[0]), "+f"(c[1]), "+f"(c[2]), "+f"(c[3])
        : "r"(a[0]), "r"(a[1]), "r"(a[2]), "r"(a[3]), "r"(b0), "r"(b1));
}
__device__ __forceinline__ void mma16816z(float* d, const uint32_t* a, uint32_t b0, uint32_t b1) {
    asm volatile(
        "mma.sync.aligned.m16n8k16.row.col.f32.bf16.bf16.f32 "
        "{%0,%1,%2,%3}, {%4,%5,%6,%7}, {%8,%9}, {%10,%10,%10,%10};"
        : "=f"(d[0]), "=f"(d[1]), "=f"(d[2]), "=f"(d[3])
        : "r"(a[0]), "r"(a[1]), "r"(a[2]), "r"(a[3]), "r"(b0), "r"(b1), "f"(0.f));
}
__device__ __forceinline__ void mma16816h(float* c, const uint32_t* a, uint32_t b0, uint32_t b1) {
    asm volatile(
        "mma.sync.aligned.m16n8k16.row.col.f32.f16.f16.f32 "
        "{%0,%1,%2,%3}, {%4,%5,%6,%7}, {%8,%9}, {%0,%1,%2,%3};"
        : "+f"(c[0]), "+f"(c[1]), "+f"(c[2]), "+f"(c[3])
        : "r"(a[0]), "r"(a[1]), "r"(a[2]), "r"(a[3]), "r"(b0), "r"(b1));
}
#define CP_COMMIT() asm volatile("cp.async.commit_group;" ::: "memory")
#define CP_WAIT(n)  asm volatile("cp.async.wait_group %0;" :: "n"(n) : "memory")

__device__ __forceinline__ uint32_t pack_bf(float x, float y) {
    __nv_bfloat162 t = __floats2bfloat162_rn(x, y);
    return *reinterpret_cast<uint32_t*>(&t);
}
__device__ __forceinline__ uint32_t pack_h(float x, float y) {
    __half2 t = __floats2half2_rn(x, y);
    return *reinterpret_cast<uint32_t*>(&t);
}
__device__ __forceinline__ void split_pair(float x, float y, uint32_t& p0, uint32_t& p1) {
    __nv_bfloat16 bx = __float2bfloat16_rn(x), by = __float2bfloat16_rn(y);
    __nv_bfloat162 t; t.x = bx; t.y = by;
    p0 = *reinterpret_cast<uint32_t*>(&t);
    p1 = pack_bf(x - __bfloat162float(bx), y - __bfloat162float(by));
}
__device__ __forceinline__ void split_pair_h(float x, float y, uint32_t& p0, uint32_t& p1) {
    __half hx = __float2half_rn(x), hy = __float2half_rn(y);
    __half2 t; t.x = hx; t.y = hy;
    p0 = *reinterpret_cast<uint32_t*>(&t);
    p1 = pack_h(x - __half2float(hx), y - __half2float(hy));
}
// async 128x128 16-bit tile -> smem rows of 272B
__device__ __forceinline__ void ld_tile_async(uint32_t dst, const void* __restrict__ srcv, int tid) {
    const char* src = reinterpret_cast<const char*>(srcv);
    #pragma unroll
    for (int i = 0; i < 8; i++) {
        int idx = tid + i * 256;
        int row = idx >> 4, ch = idx & 15;
        asm volatile("cp.async.cg.shared.global [%0], [%1], 16;" ::
            "r"(dst + (uint32_t)(row * 272 + ch * 16)), "l"(src + (size_t)row * CC * 2 + ch * 16) : "memory");
    }
}
// async 64x128 16-bit tile -> smem rows of 272B
__device__ __forceinline__ void ld_tile64_async(uint32_t dst, const void* __restrict__ srcv, int tid) {
    const char* src = reinterpret_cast<const char*>(srcv);
    #pragma unroll
    for (int i = 0; i < 4; i++) {
        int idx = tid + i * 256;
        int row = idx >> 4, ch = idx & 15;
        asm volatile("cp.async.cg.shared.global [%0], [%1], 16;" ::
            "r"(dst + (uint32_t)(row * 272 + ch * 16)), "l"(src + (size_t)row * CC * 2 + ch * 16) : "memory");
    }
}
__device__ __forceinline__ void ins8(float* tv, int* ti, float v, int idx) {
    #pragma unroll
    for (int t = 0; t < 8; t++) {
        if (v > tv[t]) {
            float a = tv[t]; tv[t] = v; v = a;
            int   b = ti[t]; ti[t] = idx; idx = b;
        }
    }
}

// ---------------- K1: fused projections -> bf16 splits (q,k), fp16 (v), skip ----------------
__global__ __launch_bounds__(256) void proj_kernel(
    const float* __restrict__ x,
    const float* __restrict__ Wq, const float* __restrict__ bq,
    const float* __restrict__ Wk, const float* __restrict__ bk,
    const float* __restrict__ Wv, const float* __restrict__ bv,
    const float* __restrict__ Ws, const float* __restrict__ bs)
{
    __shared__ float xs[32 * 129];
    const int tid = threadIdx.x;
    const int r0  = blockIdx.x * 32;
    const float SCALE = 0.08838834764831843f;

    for (int i = tid; i < 32 * CC; i += 256) {
        int r = i >> 7, c = i & 127;
        xs[r * 129 + c] = x[(r0 + r) * CC + c];
    }
    __syncthreads();

    const int ri = (tid >> 5) * 4;
    const int c0 = (tid & 31) * 4;

    const float* Wt[4] = {Wq, Wk, Wv, Ws};
    const float* bt[4] = {bq, bk, bv, bs};

    #pragma unroll
    for (int w = 0; w < 4; w++) {
        const float* W = Wt[w];
        ull acc[4][2];
        #pragma unroll
        for (int i = 0; i < 4; i++) { acc[i][0] = 0ULL; acc[i][1] = 0ULL; }

        #pragma unroll 4
        for (int k2 = 0; k2 < CC; k2++) {
            ulonglong2 wp = *reinterpret_cast<const ulonglong2*>(W + k2 * CC + c0);
            #pragma unroll
            for (int dr = 0; dr < 4; dr++) {
                ull x2 = dup2(xs[(ri + dr) * 129 + k2]);
                acc[dr][0] = ffma2(x2, wp.x, acc[dr][0]);
                acc[dr][1] = ffma2(x2, wp.y, acc[dr][1]);
            }
        }
        float4 bb = *reinterpret_cast<const float4*>(bt[w] + c0);
        #pragma unroll
        for (int dr = 0; dr < 4; dr++) {
            float2 a0 = upk(acc[dr][0]), a1 = upk(acc[dr][1]);
            int row = r0 + ri + dr;
            float ox = a0.x + bb.x, oy = a0.y + bb.y;
            float oz = a1.x + bb.z, ow = a1.y + bb.w;
            if (w == 3) {
                float4 o = {ox, oy, oz, ow};
                *reinterpret_cast<float4*>(g_skip + row * CC + c0) = o;
            } else if (w == 2) {
                uint2 u = {pack_h(ox, oy), pack_h(oz, ow)};
                *reinterpret_cast<uint2*>(g_vh + row * CC + c0) = u;
            } else {
                float s = (w == 0) ? SCALE : 1.f;
                ox *= s; oy *= s; oz *= s; ow *= s;
                uint32_t lo0, hi0, lo1, hi1;
                split_pair(ox, oy, lo0, hi0);
                split_pair(oz, ow, lo1, hi1);
                __nv_bfloat16* d0 = (w == 0) ? g_qb0 : g_kb0;
                __nv_bfloat16* d1 = (w == 0) ? g_qb1 : g_kb1;
                uint2 u0 = {lo0, lo1};
                uint2 u1 = {hi0, hi1};
                *reinterpret_cast<uint2*>(d0 + row * CC + c0) = u0;
                *reinterpret_cast<uint2*>(d1 + row * CC + c0) = u1;
            }
        }
    }
}

// ---------------- K2: flash attention — 64x64 tiles, bf16 3-prod scores, fp16 2-prod PV,
//                   4 key quarters, 2 CTAs/SM ----------------
#define AQ0 0
#define AQ1 17408
#define AK0 34816
#define AK1 52224
#define AV  69632
#define ATTN_SMEM 87040

__global__ __launch_bounds__(256, 2) void attn_mma_kernel()
{
    extern __shared__ __align__(16) char smc[];
    const uint32_t sb = smem_u32(smc);
    const int tid  = threadIdx.x, wid = tid >> 5, lane = tid & 31;
    const int qbase = blockIdx.x * 64;
    const int kofs  = blockIdx.y * QUARTN;

    const int rg = wid >> 1;       // row group (4 x 16 rows)
    const int cg = wid & 1;        // key-column group (2 x 32 keys)
    const int r0 = rg * 16;
    const int qrow = lane >> 2, qc = (lane & 3) * 2;
    const int gr0 = qbase + r0 + qrow, gr1 = gr0 + 8;

    ld_tile64_async(sb + AQ0, g_qb0 + (size_t)qbase * CC, tid);
    ld_tile64_async(sb + AQ1, g_qb1 + (size_t)qbase * CC, tid);
    CP_COMMIT();

    const uint32_t aoff = (uint32_t)((r0 + (lane & 15)) * 272 + ((lane >> 4) & 1) * 16);
    const uint32_t boff = (uint32_t)((cg * 32 + (lane & 7) + ((lane >> 4) & 1) * 8) * 272 + ((lane >> 3) & 1) * 16);
    const uint32_t voff = (uint32_t)((cg * 32 + (lane & 7) + ((lane >> 3) & 1) * 8) * 272 + ((lane >> 4) & 1) * 16);

    float pv[16][4];
    #pragma unroll
    for (int i = 0; i < 16; i++)
        #pragma unroll
        for (int j = 0; j < 4; j++) pv[i][j] = 0.f;
    float l0 = 0.f, l1 = 0.f;

    CP_WAIT(0);
    __syncthreads();   // Q resident

    for (int t = 0; t < NTA; t++) {
        const int kb = t * 64;
        ld_tile64_async(sb + AK0, g_kb0 + (size_t)(kofs + kb) * CC, tid);
        ld_tile64_async(sb + AK1, g_kb1 + (size_t)(kofs + kb) * CC, tid);
        ld_tile64_async(sb + AV,  g_vh  + (size_t)(kofs + kb) * CC, tid);
        CP_COMMIT();
        CP_WAIT(0);
        __syncthreads();

        float sc[4][4];

        // scores over this warp's 32 keys: q0k0 (+zero-init) + q1k0 + q0k1
        #pragma unroll
        for (int kc = 0; kc < 8; kc++) {
            uint32_t a0[4], a1[4];
            ldsm4(a0, sb + AQ0 + aoff + kc * 32);
            ldsm4(a1, sb + AQ1 + aoff + kc * 32);
            #pragma unroll
            for (int n2 = 0; n2 < 2; n2++) {
                uint32_t b[4];
                ldsm4(b, sb + AK0 + (uint32_t)(n2 * 16 * 272) + boff + kc * 32);
                if (kc == 0) {
                    mma16816z(sc[2 * n2],     a0, b[0], b[1]);
                    mma16816z(sc[2 * n2 + 1], a0, b[2], b[3]);
                } else {
                    mma16816(sc[2 * n2],     a0, b[0], b[1]);
                    mma16816(sc[2 * n2 + 1], a0, b[2], b[3]);
                }
                mma16816(sc[2 * n2],     a1, b[0], b[1]);
                mma16816(sc[2 * n2 + 1], a1, b[2], b[3]);
                uint32_t b1[4];
                ldsm4(b1, sb + AK1 + (uint32_t)(n2 * 16 * 272) + boff + kc * 32);
                mma16816(sc[2 * n2],     a0, b1[0], b1[1]);
                mma16816(sc[2 * n2 + 1], a0, b1[2], b1[3]);
            }
        }

        // exp + diag mask (rare uniform) + row-sum partials
        const bool hasdiag = (kofs + kb == qbase);
        if (hasdiag) {
            #pragma unroll
            for (int nt = 0; nt < 4; nt++) {
                int gc = kofs + kb + cg * 32 + nt * 8 + qc;
                float e0 = (gr0 == gc)     ? 0.f : __expf(sc[nt][0]);
                float e1 = (gr0 == gc + 1) ? 0.f : __expf(sc[nt][1]);
                float e2 = (gr1 == gc)     ? 0.f : __expf(sc[nt][2]);
                float e3 = (gr1 == gc + 1) ? 0.f : __expf(sc[nt][3]);
                sc[nt][0] = e0; sc[nt][1] = e1; sc[nt][2] = e2; sc[nt][3] = e3;
                l0 += e0 + e1; l1 += e2 + e3;
            }
        } else {
            #pragma unroll
            for (int nt = 0; nt < 4; nt++) {
                float e0 = __expf(sc[nt][0]);
                float e1 = __expf(sc[nt][1]);
                float e2 = __expf(sc[nt][2]);
                float e3 = __expf(sc[nt][3]);
                sc[nt][0] = e0; sc[nt][1] = e1; sc[nt][2] = e2; sc[nt][3] = e3;
                l0 += e0 + e1; l1 += e2 + e3;
            }
        }

        // PV over the warp's 32 keys (fp16, p = p0 + p1), all 128 v-cols
        #pragma unroll
        for (int kc2 = 0; kc2 < 2; kc2++) {
            uint32_t p0[4], p1[4];
            split_pair_h(sc[2 * kc2][0],     sc[2 * kc2][1],     p0[0], p1[0]);
            split_pair_h(sc[2 * kc2][2],     sc[2 * kc2][3],     p0[1], p1[1]);
            split_pair_h(sc[2 * kc2 + 1][0], sc[2 * kc2 + 1][1], p0[2], p1[2]);
            split_pair_h(sc[2 * kc2 + 1][2], sc[2 * kc2 + 1][3], p0[3], p1[3]);
            const uint32_t vbase = sb + AV + (uint32_t)(kc2 * 16 * 272) + voff;
            #pragma unroll
            for (int nt2 = 0; nt2 < 8; nt2++) {
                uint32_t vf[4];
                ldsm4t(vf, vbase + nt2 * 32);
                mma16816h(pv[2 * nt2],     p0, vf[0], vf[1]);
                mma16816h(pv[2 * nt2 + 1], p0, vf[2], vf[3]);
                mma16816h(pv[2 * nt2],     p1, vf[0], vf[1]);
                mma16816h(pv[2 * nt2 + 1], p1, vf[2], vf[3]);
            }
        }
        __syncthreads();   // K/V reads done before next tile's cp.async
    }

    // reduce row sums within quad (row spread over 4 lanes)
    l0 += __shfl_xor_sync(0xffffffffu, l0, 1);
    l0 += __shfl_xor_sync(0xffffffffu, l0, 2);
    l1 += __shfl_xor_sync(0xffffffffu, l1, 1);
    l1 += __shfl_xor_sync(0xffffffffu, l1, 2);

    // merge cg=1 partials into cg=0 via smem
    float* ms = reinterpret_cast<float*>(smc);          // [64][128]
    float* ls = reinterpret_cast<float*>(smc + 32768);  // [64]
    if (cg == 1) {
        #pragma unroll
        for (int nt = 0; nt < 16; nt++) {
            int c = nt * 8 + qc;
            ms[(r0 + qrow) * 128 + c]     = pv[nt][0];
            ms[(r0 + qrow) * 128 + c + 1] = pv[nt][1];
            ms[(r0 + qrow + 8) * 128 + c]     = pv[nt][2];
            ms[(r0 + qrow + 8) * 128 + c + 1] = pv[nt][3];
        }
        if ((lane & 3) == 0) {
            ls[r0 + qrow]     = l0;
            ls[r0 + qrow + 8] = l1;
        }
    }
    __syncthreads();

    if (cg == 0) {
        float* aout = g_acc + (size_t)blockIdx.y * NN * CC;
        #pragma unroll
        for (int nt = 0; nt < 16; nt++) {
            int c = nt * 8 + qc;
            float o0 = pv[nt][0] + ms[(r0 + qrow) * 128 + c];
            float o1 = pv[nt][1] + ms[(r0 + qrow) * 128 + c + 1];
            float o2 = pv[nt][2] + ms[(r0 + qrow + 8) * 128 + c];
            float o3 = pv[nt][3] + ms[(r0 + qrow + 8) * 128 + c + 1];
            *reinterpret_cast<float2*>(aout + (size_t)gr0 * CC + c) = make_float2(o0, o1);
            *reinterpret_cast<float2*>(aout + (size_t)gr1 * CC + c) = make_float2(o2, o3);
        }
        if ((lane & 3) == 0) {
            g_l[blockIdx.y * NN + gr0] = l0 + ls[r0 + qrow];
            g_l[blockIdx.y * NN + gr1] = l1 + ls[r0 + qrow + 8];
        }
    }
}

// ---------------- K3: fused combine (4 quarters) + norm + bf16 ----------------
__global__ __launch_bounds__(256) void combine_norm_kernel()
{
    int row  = blockIdx.x * 8 + (threadIdx.x >> 5);
    int lane = threadIdx.x & 31;
    size_t base = (size_t)row * CC + lane * 4;

    float inv = __fdividef(1.f, g_l[row] + g_l[NN + row] + g_l[2 * NN + row] + g_l[3 * NN + row]);
    float4 a0 = *reinterpret_cast<const float4*>(g_acc + base);
    float4 a1 = *reinterpret_cast<const float4*>(g_acc + (size_t)NN * CC + base);
    float4 a2 = *reinterpret_cast<const float4*>(g_acc + 2 * (size_t)NN * CC + base);
    float4 a3 = *reinterpret_cast<const float4*>(g_acc + 3 * (size_t)NN * CC + base);
    float4 sk = *reinterpret_cast<const float4*>(g_skip + base);

    float4 h;
    h.x = ((a0.x + a1.x) + (a2.x + a3.x)) * inv + sk.x;
    h.y = ((a0.y + a1.y) + (a2.y + a3.y)) * inv + sk.y;
    h.z = ((a0.z + a1.z) + (a2.z + a3.z)) * inv + sk.z;
    h.w = ((a0.w + a1.w) + (a2.w + a3.w)) * inv + sk.w;
    *reinterpret_cast<float4*>(g_h + base) = h;

    uint2 hb = {pack_bf(h.x, h.y), pack_bf(h.z, h.w)};
    *reinterpret_cast<uint2*>(g_hb0 + base) = hb;

    float s = h.x * h.x + h.y * h.y + h.z * h.z + h.w * h.w;
    s += __shfl_xor_sync(0xffffffffu, s, 16);
    s += __shfl_xor_sync(0xffffffffu, s, 8);
    s += __shfl_xor_sync(0xffffffffu, s, 4);
    s += __shfl_xor_sync(0xffffffffu, s, 2);
    s += __shfl_xor_sync(0xffffffffu, s, 1);
    if (lane == 0) g_norm[row] = 0.5f * s;
}

// ---------------- K4: kNN candidates — 4 key quarters, 2 CTAs/SM (R10, passing) ----------------
#define KQ0 0
#define KK0 34816
#define KNR 69632
#define KNN_SMEM 70144

__global__ __launch_bounds__(256, 2) void knn_mma_kernel()
{
    extern __shared__ __align__(16) char smc[];
    const uint32_t sb = smem_u32(smc);
    float* nr_s = reinterpret_cast<float*>(smc + KNR);

    const int tid  = threadIdx.x, wid = tid >> 5, lane = tid & 31;
    const int qbase = blockIdx.x * 128;
    const int kofs  = blockIdx.y * QUARTN;

    ld_tile_async(sb + KQ0, g_hb0 + (size_t)qbase * CC, tid);
    CP_COMMIT();

    const int r0   = wid * 16;
    const int qrow = lane >> 2, qc = (lane & 3) * 2;
    const int gr0  = qbase + r0 + qrow, gr1 = gr0 + 8;
    const int lr0  = r0 + qrow, lr1 = lr0 + 8;
    const int slot = lane & 3;

    const uint32_t aoff = (uint32_t)((r0 + (lane & 15)) * 272 + ((lane >> 4) & 1) * 16);
    const uint32_t boff = (uint32_t)(((lane & 7) + ((lane >> 4) & 1) * 8) * 272 + ((lane >> 3) & 1) * 16);

    float tv0[8], tv1[8];
    int   ti0[8], ti1[8];
    #pragma unroll
    for (int t = 0; t < 8; t++) { tv0[t] = -3e38f; tv1[t] = -3e38f; ti0[t] = 0; ti1[t] = 0; }
    float vmin0 = -3e38f, vmin1 = -3e38f;

    for (int t = 0; t < NTQ; t++) {
        const int kb = t * 128;
        ld_tile_async(sb + KK0, g_hb0 + (size_t)(kofs + kb) * CC, tid);
        CP_COMMIT();
        if (tid < 128) nr_s[tid] = g_norm[kofs + kb + tid];
        CP_WAIT(0);
        __syncthreads();

        const bool hasdiag = (kofs + kb == qbase);

        #pragma unroll
        for (int half = 0; half < 2; half++) {
            float sc[8][4];

            #pragma unroll
            for (int kc = 0; kc < 8; kc++) {
                uint32_t a[4];
                ldsm4(a, sb + KQ0 + aoff + kc * 32);
                if (kc == 0) {
                    #pragma unroll
                    for (int n2 = 0; n2 < 4; n2++) {
                        uint32_t b[4];
                        ldsm4(b, sb + KK0 + (uint32_t)((half * 4 + n2) * 16 * 272) + boff);
                        mma16816z(sc[2 * n2],     a, b[0], b[1]);
                        mma16816z(sc[2 * n2 + 1], a, b[2], b[3]);
                    }
                } else {
                    #pragma unroll
                    for (int n2 = 0; n2 < 4; n2++) {
                        uint32_t b[4];
                        ldsm4(b, sb + KK0 + (uint32_t)((half * 4 + n2) * 16 * 272) + boff + kc * 32);
                        mma16816(sc[2 * n2],     a, b[0], b[1]);
                        mma16816(sc[2 * n2 + 1], a, b[2], b[3]);
                    }
                }
            }

            #pragma unroll
            for (int s2 = 0; s2 < 8; s2++) {
                int c = (half * 8 + s2) * 8 + qc;
                float nr0 = nr_s[c], nr1 = nr_s[c + 1];
                sc[s2][0] -= nr0;
                sc[s2][1] -= nr1;
                sc[s2][2] -= nr0;
                sc[s2][3] -= nr1;
            }
            if (hasdiag) {
                #pragma unroll
                for (int s2 = 0; s2 < 8; s2++) {
                    int gc = kofs + kb + (half * 8 + s2) * 8 + qc;
                    if (gr0 == gc)     sc[s2][0] = -3e38f;
                    if (gr0 == gc + 1) sc[s2][1] = -3e38f;
                    if (gr1 == gc)     sc[s2][2] = -3e38f;
                    if (gr1 == gc + 1) sc[s2][3] = -3e38f;
                }
            }
            float m0 = -3e38f, m1 = -3e38f;
            #pragma unroll
            for (int s2 = 0; s2 < 8; s2++) {
                m0 = fmaxf(m0, fmaxf(sc[s2][0], sc[s2][1]));
                m1 = fmaxf(m1, fmaxf(sc[s2][2], sc[s2][3]));
            }
            if (m0 > vmin0) {
                #pragma unroll
                for (int s2 = 0; s2 < 8; s2++) {
                    int gc = kofs + kb + (half * 8 + s2) * 8 + qc;
                    if (sc[s2][0] > vmin0) { ins8(tv0, ti0, sc[s2][0], gc);     vmin0 = tv0[7]; }
                    if (sc[s2][1] > vmin0) { ins8(tv0, ti0, sc[s2][1], gc + 1); vmin0 = tv0[7]; }
                }
            }
            if (m1 > vmin1) {
                #pragma unroll
                for (int s2 = 0; s2 < 8; s2++) {
                    int gc = kofs + kb + (half * 8 + s2) * 8 + qc;
                    if (sc[s2][2] > vmin1) { ins8(tv1, ti1, sc[s2][2], gc);     vmin1 = tv1[7]; }
                    if (sc[s2][3] > vmin1) { ins8(tv1, ti1, sc[s2][3], gc + 1); vmin1 = tv1[7]; }
                }
            }
        }
        __syncthreads();
    }

    float* mv = reinterpret_cast<float*>(smc);            // [128][32]
    int*   mi = reinterpret_cast<int*>(smc + 16384);
    #pragma unroll
    for (int t = 0; t < 8; t++) {
        mv[lr0 * 32 + slot * 8 + t] = tv0[t];
        mi[lr0 * 32 + slot * 8 + t] = ti0[t];
        mv[lr1 * 32 + slot * 8 + t] = tv1[t];
        mi[lr1 * 32 + slot * 8 + t] = ti1[t];
    }
    __syncthreads();

    if (tid < 128) {
        const float* rv = mv + tid * 32;
        const int*   ri = mi + tid * 32;
        float bv[NCQ]; int bi[NCQ];
        #pragma unroll
        for (int t = 0; t < NCQ; t++) { bv[t] = -3e38f; bi[t] = 0; }
        float vm = -3e38f;
        #pragma unroll 4
        for (int j = 0; j < 32; j++) {
            float v = rv[j];
            if (v > vm) {
                float cv = v; int ci2 = ri[j];
                #pragma unroll
                for (int t = 0; t < NCQ; t++) {
                    if (cv > bv[t]) {
                        float a = bv[t]; bv[t] = cv; cv = a;
                        int   b = bi[t]; bi[t] = ci2; ci2 = b;
                    }
                }
                vm = bv[NCQ - 1];
            }
        }
        int* outi = g_ci8 + ((size_t)blockIdx.y * NN + qbase + tid) * NCQ;
        #pragma unroll
        for (int t = 0; t < NCQ; t++) outi[t] = bi[t];
    }
}

// ---------------- K5: exact fp32 rescore of 32 candidates -> top-7 ----------------
__global__ __launch_bounds__(256) void knn_rescore_kernel()
{
    int node = (blockIdx.x * 256 + threadIdx.x) >> 5;
    int lane = threadIdx.x & 31;

    float4 hv = *reinterpret_cast<const float4*>(g_h + (size_t)node * CC + lane * 4);
    int quarter = lane >> 3, slot = lane & 7;
    int ci = g_ci8[((size_t)quarter * NN + node) * NCQ + slot];

    float myv = -3e38f;
    for (int c = 0; c < 32; c++) {
        int cj = __shfl_sync(0xffffffffu, ci, c);
        float4 hc = *reinterpret_cast<const float4*>(g_h + (size_t)cj * CC + lane * 4);
        float p = hv.x * hc.x + hv.y * hc.y + hv.z * hc.z + hv.w * hc.w;
        #pragma unroll
        for (int m = 16; m >= 1; m >>= 1) p += __shfl_xor_sync(0xffffffffu, p, m);
        if (lane == c) myv = p - g_norm[cj];
    }

    float v = myv; int idx = ci;
    #pragma unroll
    for (int t = 0; t < KNBR; t++) {
        float bv = v; int bidx = idx;
        #pragma unroll
        for (int m = 16; m >= 1; m >>= 1) {
            float ov = __shfl_xor_sync(0xffffffffu, bv, m);
            int   oi = __shfl_xor_sync(0xffffffffu, bidx, m);
            if (ov > bv || (ov == bv && oi < bidx)) { bv = ov; bidx = oi; }
        }
        if (lane == 0) g_idx[node * KNBR + t] = bidx;
        if (idx == bidx) v = -3.3e38f;
    }
}

// ---------------- K6: m1 = h @ W1 ----------------
__global__ __launch_bounds__(256) void gcn1_gemm(const float* __restrict__ W1)
{
    __shared__ float xs[32 * 129];
    const int tid = threadIdx.x;
    const int r0  = blockIdx.x * 32;

    for (int i = tid; i < 32 * CC; i += 256) {
        int r = i >> 7, c = i & 127;
        xs[r * 129 + c] = g_h[(r0 + r) * CC + c];
    }
    __syncthreads();

    const int ri = (tid >> 5) * 4;
    const int c0 = (tid & 31) * 4;

    ull acc[4][2];
    #pragma unroll
    for (int i = 0; i < 4; i++) { acc[i][0] = 0ULL; acc[i][1] = 0ULL; }

    #pragma unroll 4
    for (int k2 = 0; k2 < CC; k2++) {
        ulonglong2 wp = *reinterpret_cast<const ulonglong2*>(W1 + k2 * CC + c0);
        #pragma unroll
        for (int dr = 0; dr < 4; dr++) {
            ull x2 = dup2(xs[(ri + dr) * 129 + k2]);
            acc[dr][0] = ffma2(x2, wp.x, acc[dr][0]);
            acc[dr][1] = ffma2(x2, wp.y, acc[dr][1]);
        }
    }
    #pragma unroll
    for (int dr = 0; dr < 4; dr++) {
        float2 a0 = upk(acc[dr][0]), a1 = upk(acc[dr][1]);
        float4 o = {a0.x, a0.y, a1.x, a1.y};
        *reinterpret_cast<float4*>(g_m1 + (r0 + ri + dr) * CC + c0) = o;
    }
}

// ---------------- K7: GCN layer-1 gather + relu ----------------
__global__ __launch_bounds__(128) void gather1(const float* __restrict__ b1)
{
    int node = blockIdx.x;
    int c    = threadIdx.x;
    float s = g_m1[node * CC + c];
    #pragma unroll
    for (int t = 0; t < KNBR; t++) {
        int nb = g_idx[node * KNBR + t];
        s += g_m1[nb * CC + c];
    }
    g_h1[node * CC + c] = fmaxf(s * 0.125f + b1[c], 0.f);
}

// ---------------- K8: m2 = h1 @ W2 ----------------
__global__ __launch_bounds__(256) void m2_kernel(const float* __restrict__ W2)
{
    int row  = blockIdx.x * 8 + (threadIdx.x >> 5);
    int lane = threadIdx.x & 31;
    float s = 0.f;
    for (int c = lane; c < CC; c += 32) s += g_h1[row * CC + c] * W2[c];
    s += __shfl_xor_sync(0xffffffffu, s, 16);
    s += __shfl_xor_sync(0xffffffffu, s, 8);
    s += __shfl_xor_sync(0xffffffffu, s, 4);
    s += __shfl_xor_sync(0xffffffffu, s, 2);
    s += __shfl_xor_sync(0xffffffffu, s, 1);
    if (lane == 0) g_m2[row] = s;
}

// ---------------- K9: GCN layer-2 gather -> output ----------------
__global__ __launch_bounds__(256) void out_kernel(const float* __restrict__ b2,
                                                  float* __restrict__ out)
{
    int n = blockIdx.x * 256 + threadIdx.x;
    float s = g_m2[n];
    #pragma unroll
    for (int t = 0; t < KNBR; t++) s += g_m2[g_idx[n * KNBR + t]];
    out[n] = s * 0.125f + b2[0];
}

// ---------------- launch ----------------
extern "C" void kernel_launch(void* const* d_in, const int* in_sizes, int n_in,
                              void* d_out, int out_size)
{
    const float* x   = (const float*)d_in[0];
    const float* Wq  = (const float*)d_in[1];
    const float* bq  = (const float*)d_in[2];
    const float* Wk  = (const float*)d_in[3];
    const float* bk  = (const float*)d_in[4];
    const float* Wv  = (const float*)d_in[5];
    const float* bv  = (const float*)d_in[6];
    const float* Wsk = (const float*)d_in[7];
    const float* bsk = (const float*)d_in[8];
    const float* W1  = (const float*)d_in[9];
    const float* b1  = (const float*)d_in[10];
    const float* W2  = (const float*)d_in[11];
    const float* b2  = (const float*)d_in[12];
    float* out = (float*)d_out;

    cudaFuncSetAttribute(attn_mma_kernel, cudaFuncAttributeMaxDynamicSharedMemorySize, ATTN_SMEM);
    cudaFuncSetAttribute(knn_mma_kernel,  cudaFuncAttributeMaxDynamicSharedMemorySize, KNN_SMEM);

    proj_kernel<<<NN / 32, 256>>>(x, Wq, bq, Wk, bk, Wv, bv, Wsk, bsk);
    attn_mma_kernel<<<dim3(NN / 64, 4), 256, ATTN_SMEM>>>();
    combine_norm_kernel<<<NN / 8, 256>>>();
    knn_mma_kernel<<<dim3(NN / 128, 4), 256, KNN_SMEM>>>();
    knn_rescore_kernel<<<NN / 8, 256>>>();
    gcn1_gemm<<<NN / 32, 256>>>(W1);
    gather1<<<NN, CC>>>(b1);
    m2_kernel<<<NN / 8, 256>>>(W2);
    out_kernel<<<NN / 256, 256>>>(b2, out);
}

// round 15
// speedup vs baseline: 1.0934x; 1.0934x over previous
#include <cuda_runtime.h>
#include <cuda_bf16.h>
#include <cuda_fp16.h>
#include <cstdint>

#define NN    8192
#define CC    128
#define KNBR  7
#define HALFN 4096
#define QUARTN 2048
#define NTH   (HALFN / 128)
#define NTQ   (QUARTN / 128)
#define NCQ   8

typedef unsigned long long ull;

// ---------------- device scratch ----------------
__device__ float g_skip[NN * CC];
__device__ float g_h[NN * CC];
__device__ float g_acc[2 * NN * CC];
__device__ float g_l[2 * NN];
__device__ float g_norm[NN];
__device__ int   g_ci8[4 * NN * NCQ];
__device__ int   g_idx[NN * KNBR];
__device__ float g_m1[NN * CC];
__device__ float g_h1[NN * CC];
__device__ float g_m2[NN];
__device__ __nv_bfloat16 g_qb0[NN * CC], g_qb1[NN * CC];
__device__ __nv_bfloat16 g_kb0[NN * CC], g_kb1[NN * CC];
__device__ __half        g_vh[NN * CC];
__device__ __nv_bfloat16 g_hb0[NN * CC], g_hb1[NN * CC];
__device__ __nv_bfloat16 g_w1t0[CC * CC], g_w1t1[CC * CC];   // W1^T splits

// ---------------- packed fp32x2 (SIMT proj) ----------------
__device__ __forceinline__ ull ffma2(ull a, ull b, ull c) {
    ull d;
    asm("fma.rn.f32x2 %0, %1, %2, %3;" : "=l"(d) : "l"(a), "l"(b), "l"(c));
    return d;
}
__device__ __forceinline__ ull dup2(float x) {
    ull d;
    asm("mov.b64 %0, {%1, %1};" : "=l"(d) : "f"(x));
    return d;
}
__device__ __forceinline__ float2 upk(ull v) {
    float2 r;
    asm("mov.b64 {%0, %1}, %2;" : "=f"(r.x), "=f"(r.y) : "l"(v));
    return r;
}

// ---------------- mma / ldmatrix / cp.async helpers ----------------
__device__ __forceinline__ uint32_t smem_u32(const void* p) {
    uint32_t a;
    asm("{ .reg .u64 t; cvta.to.shared.u64 t, %1; cvt.u32.u64 %0, t; }" : "=r"(a) : "l"(p));
    return a;
}
__device__ __forceinline__ void ldsm4(uint32_t* r, uint32_t a) {
    asm volatile("ldmatrix.sync.aligned.m8n8.x4.shared.b16 {%0,%1,%2,%3}, [%4];"
                 : "=r"(r[0]), "=r"(r[1]), "=r"(r[2]), "=r"(r[3]) : "r"(a));
}
__device__ __forceinline__ void ldsm4t(uint32_t* r, uint32_t a) {
    asm volatile("ldmatrix.sync.aligned.m8n8.x4.trans.shared.b16 {%0,%1,%2,%3}, [%4];"
                 : "=r"(r[0]), "=r"(r[1]), "=r"(r[2]), "=r"(r[3]) : "r"(a));
}
__device__ __forceinline__ void mma16816(float* c, const uint32_t* a, uint32_t b0, uint32_t b1) {
    asm volatile(
        "mma.sync.aligned.m16n8k16.row.col.f32.bf16.bf16.f32 "
        "{%0,%1,%2,%3}, {%4,%5,%6,%7}, {%8,%9}, {%0,%1,%2,%3};"
        : "+f"(c[0]), "+f"(c[1]), "+f"(c[2]), "+f"(c[3])
        : "r"(a[0]), "r"(a[1]), "r"(a[2]), "r"(a[3]), "r"(b0), "r"(b1));
}
__device__ __forceinline__ void mma16816z(float* d, const uint32_t* a, uint32_t b0, uint32_t b1) {
    asm volatile(
        "mma.sync.aligned.m16n8k16.row.col.f32.bf16.bf16.f32 "
        "{%0,%1,%2,%3}, {%4,%5,%6,%7}, {%8,%9}, {%10,%10,%10,%10};"
        : "=f"(d[0]), "=f"(d[1]), "=f"(d[2]), "=f"(d[3])
        : "r"(a[0]), "r"(a[1]), "r"(a[2]), "r"(a[3]), "r"(b0), "r"(b1), "f"(0.f));
}
__device__ __forceinline__ void mma16816h(float* c, const uint32_t* a, uint32_t b0, uint32_t b1) {
    asm volatile(
        "mma.sync.aligned.m16n8k16.row.col.f32.f16.f16.f32 "
        "{%0,%1,%2,%3}, {%4,%5,%6,%7}, {%8,%9}, {%0,%1,%2,%3};"
        : "+f"(c[0]), "+f"(c[1]), "+f"(c[2]), "+f"(c[3])
        : "r"(a[0]), "r"(a[1]), "r"(a[2]), "r"(a[3]), "r"(b0), "r"(b1));
}
#define CP_COMMIT() asm volatile("cp.async.commit_group;" ::: "memory")
#define CP_WAIT(n)  asm volatile("cp.async.wait_group %0;" :: "n"(n) : "memory")

__device__ __forceinline__ uint32_t pack_bf(float x, float y) {
    __nv_bfloat162 t = __floats2bfloat162_rn(x, y);
    return *reinterpret_cast<uint32_t*>(&t);
}
__device__ __forceinline__ uint32_t pack_h(float x, float y) {
    __half2 t = __floats2half2_rn(x, y);
    return *reinterpret_cast<uint32_t*>(&t);
}
__device__ __forceinline__ void split_pair(float x, float y, uint32_t& p0, uint32_t& p1) {
    __nv_bfloat16 bx = __float2bfloat16_rn(x), by = __float2bfloat16_rn(y);
    __nv_bfloat162 t; t.x = bx; t.y = by;
    p0 = *reinterpret_cast<uint32_t*>(&t);
    p1 = pack_bf(x - __bfloat162float(bx), y - __bfloat162float(by));
}
__device__ __forceinline__ void split_pair_h(float x, float y, uint32_t& p0, uint32_t& p1) {
    __half hx = __float2half_rn(x), hy = __float2half_rn(y);
    __half2 t; t.x = hx; t.y = hy;
    p0 = *reinterpret_cast<uint32_t*>(&t);
    p1 = pack_h(x - __half2float(hx), y - __half2float(hy));
}
// async 128x128 16-bit tile -> smem rows of 272B
__device__ __forceinline__ void ld_tile_async(uint32_t dst, const void* __restrict__ srcv, int tid) {
    const char* src = reinterpret_cast<const char*>(srcv);
    #pragma unroll
    for (int i = 0; i < 8; i++) {
        int idx = tid + i * 256;
        int row = idx >> 4, ch = idx & 15;
        asm volatile("cp.async.cg.shared.global [%0], [%1], 16;" ::
            "r"(dst + (uint32_t)(row * 272 + ch * 16)), "l"(src + (size_t)row * CC * 2 + ch * 16) : "memory");
    }
}
// async 64x128 16-bit tile -> smem rows of 272B
__device__ __forceinline__ void ld_tile64_async(uint32_t dst, const void* __restrict__ srcv, int tid) {
    const char* src = reinterpret_cast<const char*>(srcv);
    #pragma unroll
    for (int i = 0; i < 4; i++) {
        int idx = tid + i * 256;
        int row = idx >> 4, ch = idx & 15;
        asm volatile("cp.async.cg.shared.global [%0], [%1], 16;" ::
            "r"(dst + (uint32_t)(row * 272 + ch * 16)), "l"(src + (size_t)row * CC * 2 + ch * 16) : "memory");
    }
}
__device__ __forceinline__ void ins8(float* tv, int* ti, float v, int idx) {
    #pragma unroll
    for (int t = 0; t < 8; t++) {
        if (v > tv[t]) {
            float a = tv[t]; tv[t] = v; v = a;
            int   b = ti[t]; ti[t] = idx; idx = b;
        }
    }
}

// ---------------- K0: transpose + bf16-split W1 only ----------------
__global__ __launch_bounds__(256) void split_w1_kernel(const float* __restrict__ W1)
{
    int i = blockIdx.x * 256 + threadIdx.x;
    int k = i >> 7, n = i & 127;
    float v = W1[i];
    __nv_bfloat16 b0 = __float2bfloat16_rn(v);
    g_w1t0[n * CC + k] = b0;
    g_w1t1[n * CC + k] = __float2bfloat16_rn(v - __bfloat162float(b0));
}

// ---------------- K1: fused projections — R10 SIMT fp32 version (verbatim) ----------------
__global__ __launch_bounds__(256) void proj_kernel(
    const float* __restrict__ x,
    const float* __restrict__ Wq, const float* __restrict__ bq,
    const float* __restrict__ Wk, const float* __restrict__ bk,
    const float* __restrict__ Wv, const float* __restrict__ bv,
    const float* __restrict__ Ws, const float* __restrict__ bs)
{
    __shared__ float xs[32 * 129];
    const int tid = threadIdx.x;
    const int r0  = blockIdx.x * 32;
    const float SCALE = 0.08838834764831843f;

    for (int i = tid; i < 32 * CC; i += 256) {
        int r = i >> 7, c = i & 127;
        xs[r * 129 + c] = x[(r0 + r) * CC + c];
    }
    __syncthreads();

    const int ri = (tid >> 5) * 4;
    const int c0 = (tid & 31) * 4;

    const float* Wt[4] = {Wq, Wk, Wv, Ws};
    const float* bt[4] = {bq, bk, bv, bs};

    #pragma unroll
    for (int w = 0; w < 4; w++) {
        const float* W = Wt[w];
        ull acc[4][2];
        #pragma unroll
        for (int i = 0; i < 4; i++) { acc[i][0] = 0ULL; acc[i][1] = 0ULL; }

        #pragma unroll 4
        for (int k2 = 0; k2 < CC; k2++) {
            ulonglong2 wp = *reinterpret_cast<const ulonglong2*>(W + k2 * CC + c0);
            #pragma unroll
            for (int dr = 0; dr < 4; dr++) {
                ull x2 = dup2(xs[(ri + dr) * 129 + k2]);
                acc[dr][0] = ffma2(x2, wp.x, acc[dr][0]);
                acc[dr][1] = ffma2(x2, wp.y, acc[dr][1]);
            }
        }
        float4 bb = *reinterpret_cast<const float4*>(bt[w] + c0);
        #pragma unroll
        for (int dr = 0; dr < 4; dr++) {
            float2 a0 = upk(acc[dr][0]), a1 = upk(acc[dr][1]);
            int row = r0 + ri + dr;
            float ox = a0.x + bb.x, oy = a0.y + bb.y;
            float oz = a1.x + bb.z, ow = a1.y + bb.w;
            if (w == 3) {
                float4 o = {ox, oy, oz, ow};
                *reinterpret_cast<float4*>(g_skip + row * CC + c0) = o;
            } else if (w == 2) {
                uint2 u = {pack_h(ox, oy), pack_h(oz, ow)};
                *reinterpret_cast<uint2*>(g_vh + row * CC + c0) = u;
            } else {
                float s = (w == 0) ? SCALE : 1.f;
                ox *= s; oy *= s; oz *= s; ow *= s;
                uint32_t lo0, hi0, lo1, hi1;
                split_pair(ox, oy, lo0, hi0);
                split_pair(oz, ow, lo1, hi1);
                __nv_bfloat16* d0 = (w == 0) ? g_qb0 : g_kb0;
                __nv_bfloat16* d1 = (w == 0) ? g_qb1 : g_kb1;
                uint2 u0 = {lo0, lo1};
                uint2 u1 = {hi0, hi1};
                *reinterpret_cast<uint2*>(d0 + row * CC + c0) = u0;
                *reinterpret_cast<uint2*>(d1 + row * CC + c0) = u1;
            }
        }
    }
}

// ---------------- K2: flash attention (R10-winning version, verbatim) ----------------
#define AQ0 0
#define AQ1 34816
#define AK0 69632
#define AK1 104448
#define AV0 139264
#define ATTN_SMEM 174080

__global__ __launch_bounds__(256, 1) void attn_mma_kernel()
{
    extern __shared__ __align__(16) char smc[];
    const uint32_t sb = smem_u32(smc);
    const int tid  = threadIdx.x, wid = tid >> 5, lane = tid & 31;
    const int qbase = blockIdx.x * 128;
    const int kofs  = blockIdx.y * HALFN;

    ld_tile_async(sb + AQ0, g_qb0 + (size_t)qbase * CC, tid);
    ld_tile_async(sb + AQ1, g_qb1 + (size_t)qbase * CC, tid);
    CP_COMMIT();
    ld_tile_async(sb + AK0, g_kb0 + (size_t)kofs * CC, tid);
    ld_tile_async(sb + AK1, g_kb1 + (size_t)kofs * CC, tid);
    CP_COMMIT();
    ld_tile_async(sb + AV0, g_vh + (size_t)kofs * CC, tid);
    CP_COMMIT();

    const int r0   = wid * 16;
    const int qrow = lane >> 2, qc = (lane & 3) * 2;
    const int gr0  = qbase + r0 + qrow, gr1 = gr0 + 8;

    const uint32_t aoff = (uint32_t)((r0 + (lane & 15)) * 272 + ((lane >> 4) & 1) * 16);
    const uint32_t boff = (uint32_t)(((lane & 7) + ((lane >> 4) & 1) * 8) * 272 + ((lane >> 3) & 1) * 16);
    const uint32_t voff = (uint32_t)(((lane & 7) + ((lane >> 3) & 1) * 8) * 272 + ((lane >> 4) & 1) * 16);

    float pv[16][4];
    #pragma unroll
    for (int i = 0; i < 16; i++)
        #pragma unroll
        for (int j = 0; j < 4; j++) pv[i][j] = 0.f;
    float l0 = 0.f, l1 = 0.f;

    CP_WAIT(1);
    __syncthreads();

    for (int t = 0; t < NTH; t++) {
        const int kb = t * 128;
        const bool more = (t + 1 < NTH);

        float sc[16][4];

        #pragma unroll
        for (int kc = 0; kc < 8; kc++) {
            uint32_t a0[4], a1[4];
            ldsm4(a0, sb + AQ0 + aoff + kc * 32);
            ldsm4(a1, sb + AQ1 + aoff + kc * 32);
            if (kc == 0) {
                #pragma unroll
                for (int nt2 = 0; nt2 < 8; nt2++) {
                    uint32_t b[4];
                    ldsm4(b, sb + AK0 + (uint32_t)(nt2 * 16 * 272) + boff);
                    mma16816z(sc[2 * nt2],     a0, b[0], b[1]);
                    mma16816z(sc[2 * nt2 + 1], a0, b[2], b[3]);
                    mma16816(sc[2 * nt2],     a1, b[0], b[1]);
                    mma16816(sc[2 * nt2 + 1], a1, b[2], b[3]);
                }
            } else {
                #pragma unroll
                for (int nt2 = 0; nt2 < 8; nt2++) {
                    uint32_t b[4];
                    ldsm4(b, sb + AK0 + (uint32_t)(nt2 * 16 * 272) + boff + kc * 32);
                    mma16816(sc[2 * nt2],     a0, b[0], b[1]);
                    mma16816(sc[2 * nt2 + 1], a0, b[2], b[3]);
                    mma16816(sc[2 * nt2],     a1, b[0], b[1]);
                    mma16816(sc[2 * nt2 + 1], a1, b[2], b[3]);
                }
            }
            #pragma unroll
            for (int nt2 = 0; nt2 < 8; nt2++) {
                uint32_t b[4];
                ldsm4(b, sb + AK1 + (uint32_t)(nt2 * 16 * 272) + boff + kc * 32);
                mma16816(sc[2 * nt2],     a0, b[0], b[1]);
                mma16816(sc[2 * nt2 + 1], a0, b[2], b[3]);
            }
        }

        float rs0 = 0.f, rs1 = 0.f;
        if (kofs + kb == qbase) {
            #pragma unroll
            for (int nt = 0; nt < 16; nt++) {
                int gc = kofs + kb + nt * 8 + qc;
                float e0 = (gr0 == gc)     ? 0.f : __expf(sc[nt][0]);
                float e1 = (gr0 == gc + 1) ? 0.f : __expf(sc[nt][1]);
                float e2 = (gr1 == gc)     ? 0.f : __expf(sc[nt][2]);
                float e3 = (gr1 == gc + 1) ? 0.f : __expf(sc[nt][3]);
                sc[nt][0] = e0; sc[nt][1] = e1; sc[nt][2] = e2; sc[nt][3] = e3;
                rs0 += e0 + e1; rs1 += e2 + e3;
            }
        } else {
            #pragma unroll
            for (int nt = 0; nt < 16; nt++) {
                float e0 = __expf(sc[nt][0]);
                float e1 = __expf(sc[nt][1]);
                float e2 = __expf(sc[nt][2]);
                float e3 = __expf(sc[nt][3]);
                sc[nt][0] = e0; sc[nt][1] = e1; sc[nt][2] = e2; sc[nt][3] = e3;
                rs0 += e0 + e1; rs1 += e2 + e3;
            }
        }
        rs0 += __shfl_xor_sync(0xffffffffu, rs0, 1);
        rs0 += __shfl_xor_sync(0xffffffffu, rs0, 2);
        rs1 += __shfl_xor_sync(0xffffffffu, rs1, 1);
        rs1 += __shfl_xor_sync(0xffffffffu, rs1, 2);
        l0 += rs0; l1 += rs1;

        CP_WAIT(0);
        __syncthreads();

        if (more) {
            ld_tile_async(sb + AK0, g_kb0 + (size_t)(kofs + kb + 128) * CC, tid);
            ld_tile_async(sb + AK1, g_kb1 + (size_t)(kofs + kb + 128) * CC, tid);
            CP_COMMIT();
        }

        #pragma unroll
        for (int kc = 0; kc < 8; kc++) {
            uint32_t p0[4], p1[4];
            split_pair_h(sc[2 * kc][0],     sc[2 * kc][1],     p0[0], p1[0]);
            split_pair_h(sc[2 * kc][2],     sc[2 * kc][3],     p0[1], p1[1]);
            split_pair_h(sc[2 * kc + 1][0], sc[2 * kc + 1][1], p0[2], p1[2]);
            split_pair_h(sc[2 * kc + 1][2], sc[2 * kc + 1][3], p0[3], p1[3]);
            #pragma unroll
            for (int nt2 = 0; nt2 < 8; nt2++) {
                uint32_t vf[4];
                ldsm4t(vf, sb + AV0 + (uint32_t)(kc * 16 * 272) + voff + nt2 * 32);
                mma16816h(pv[2 * nt2],     p0, vf[0], vf[1]);
                mma16816h(pv[2 * nt2 + 1], p0, vf[2], vf[3]);
                mma16816h(pv[2 * nt2],     p1, vf[0], vf[1]);
                mma16816h(pv[2 * nt2 + 1], p1, vf[2], vf[3]);
            }
        }
        __syncthreads();

        if (more) {
            ld_tile_async(sb + AV0, g_vh + (size_t)(kofs + kb + 128) * CC, tid);
            CP_COMMIT();
            CP_WAIT(1);
            __syncthreads();
        }
    }

    float* aout = g_acc + (size_t)blockIdx.y * NN * CC;
    #pragma unroll
    for (int nt = 0; nt < 16; nt++) {
        int c = nt * 8 + qc;
        *reinterpret_cast<float2*>(aout + (size_t)gr0 * CC + c) = make_float2(pv[nt][0], pv[nt][1]);
        *reinterpret_cast<float2*>(aout + (size_t)gr1 * CC + c) = make_float2(pv[nt][2], pv[nt][3]);
    }
    if ((lane & 3) == 0) {
        g_l[blockIdx.y * NN + gr0] = l0;
        g_l[blockIdx.y * NN + gr1] = l1;
    }
}

// ---------------- K3: fused combine + norm + bf16 2-split of h ----------------
__global__ __launch_bounds__(256) void combine_norm_kernel()
{
    int row  = blockIdx.x * 8 + (threadIdx.x >> 5);
    int lane = threadIdx.x & 31;
    size_t base = (size_t)row * CC + lane * 4;

    float inv = __fdividef(1.f, g_l[row] + g_l[NN + row]);
    float4 a0 = *reinterpret_cast<const float4*>(g_acc + base);
    float4 a1 = *reinterpret_cast<const float4*>(g_acc + (size_t)NN * CC + base);
    float4 sk = *reinterpret_cast<const float4*>(g_skip + base);

    float4 h;
    h.x = (a0.x + a1.x) * inv + sk.x;
    h.y = (a0.y + a1.y) * inv + sk.y;
    h.z = (a0.z + a1.z) * inv + sk.z;
    h.w = (a0.w + a1.w) * inv + sk.w;
    *reinterpret_cast<float4*>(g_h + base) = h;

    uint32_t lo0, hi0, lo1, hi1;
    split_pair(h.x, h.y, lo0, hi0);
    split_pair(h.z, h.w, lo1, hi1);
    uint2 u0 = {lo0, lo1};
    uint2 u1 = {hi0, hi1};
    *reinterpret_cast<uint2*>(g_hb0 + base) = u0;
    *reinterpret_cast<uint2*>(g_hb1 + base) = u1;

    float s = h.x * h.x + h.y * h.y + h.z * h.z + h.w * h.w;
    s += __shfl_xor_sync(0xffffffffu, s, 16);
    s += __shfl_xor_sync(0xffffffffu, s, 8);
    s += __shfl_xor_sync(0xffffffffu, s, 4);
    s += __shfl_xor_sync(0xffffffffu, s, 2);
    s += __shfl_xor_sync(0xffffffffu, s, 1);
    if (lane == 0) g_norm[row] = 0.5f * s;
}

// ---------------- K4: kNN candidates — 4 key quarters, 2 CTAs/SM (R10, passing) ----------------
#define KQ0 0
#define KK0 34816
#define KNR 69632
#define KNN_SMEM 70144

__global__ __launch_bounds__(256, 2) void knn_mma_kernel()
{
    extern __shared__ __align__(16) char smc[];
    const uint32_t sb = smem_u32(smc);
    float* nr_s = reinterpret_cast<float*>(smc + KNR);

    const int tid  = threadIdx.x, wid = tid >> 5, lane = tid & 31;
    const int qbase = blockIdx.x * 128;
    const int kofs  = blockIdx.y * QUARTN;

    ld_tile_async(sb + KQ0, g_hb0 + (size_t)qbase * CC, tid);
    CP_COMMIT();

    const int r0   = wid * 16;
    const int qrow = lane >> 2, qc = (lane & 3) * 2;
    const int gr0  = qbase + r0 + qrow, gr1 = gr0 + 8;
    const int lr0  = r0 + qrow, lr1 = lr0 + 8;
    const int slot = lane & 3;

    const uint32_t aoff = (uint32_t)((r0 + (lane & 15)) * 272 + ((lane >> 4) & 1) * 16);
    const uint32_t boff = (uint32_t)(((lane & 7) + ((lane >> 4) & 1) * 8) * 272 + ((lane >> 3) & 1) * 16);

    float tv0[8], tv1[8];
    int   ti0[8], ti1[8];
    #pragma unroll
    for (int t = 0; t < 8; t++) { tv0[t] = -3e38f; tv1[t] = -3e38f; ti0[t] = 0; ti1[t] = 0; }
    float vmin0 = -3e38f, vmin1 = -3e38f;

    for (int t = 0; t < NTQ; t++) {
        const int kb = t * 128;
        ld_tile_async(sb + KK0, g_hb0 + (size_t)(kofs + kb) * CC, tid);
        CP_COMMIT();
        if (tid < 128) nr_s[tid] = g_norm[kofs + kb + tid];
        CP_WAIT(0);
        __syncthreads();

        const bool hasdiag = (kofs + kb == qbase);

        #pragma unroll
        for (int half = 0; half < 2; half++) {
            float sc[8][4];

            #pragma unroll
            for (int kc = 0; kc < 8; kc++) {
                uint32_t a[4];
                ldsm4(a, sb + KQ0 + aoff + kc * 32);
                if (kc == 0) {
                    #pragma unroll
                    for (int n2 = 0; n2 < 4; n2++) {
                        uint32_t b[4];
                        ldsm4(b, sb + KK0 + (uint32_t)((half * 4 + n2) * 16 * 272) + boff);
                        mma16816z(sc[2 * n2],     a, b[0], b[1]);
                        mma16816z(sc[2 * n2 + 1], a, b[2], b[3]);
                    }
                } else {
                    #pragma unroll
                    for (int n2 = 0; n2 < 4; n2++) {
                        uint32_t b[4];
                        ldsm4(b, sb + KK0 + (uint32_t)((half * 4 + n2) * 16 * 272) + boff + kc * 32);
                        mma16816(sc[2 * n2],     a, b[0], b[1]);
                        mma16816(sc[2 * n2 + 1], a, b[2], b[3]);
                    }
                }
            }

            #pragma unroll
            for (int s2 = 0; s2 < 8; s2++) {
                int c = (half * 8 + s2) * 8 + qc;
                float nr0 = nr_s[c], nr1 = nr_s[c + 1];
                sc[s2][0] -= nr0;
                sc[s2][1] -= nr1;
                sc[s2][2] -= nr0;
                sc[s2][3] -= nr1;
            }
            if (hasdiag) {
                #pragma unroll
                for (int s2 = 0; s2 < 8; s2++) {
                    int gc = kofs + kb + (half * 8 + s2) * 8 + qc;
                    if (gr0 == gc)     sc[s2][0] = -3e38f;
                    if (gr0 == gc + 1) sc[s2][1] = -3e38f;
                    if (gr1 == gc)     sc[s2][2] = -3e38f;
                    if (gr1 == gc + 1) sc[s2][3] = -3e38f;
                }
            }
            float m0 = -3e38f, m1 = -3e38f;
            #pragma unroll
            for (int s2 = 0; s2 < 8; s2++) {
                m0 = fmaxf(m0, fmaxf(sc[s2][0], sc[s2][1]));
                m1 = fmaxf(m1, fmaxf(sc[s2][2], sc[s2][3]));
            }
            if (m0 > vmin0) {
                #pragma unroll
                for (int s2 = 0; s2 < 8; s2++) {
                    int gc = kofs + kb + (half * 8 + s2) * 8 + qc;
                    if (sc[s2][0] > vmin0) { ins8(tv0, ti0, sc[s2][0], gc);     vmin0 = tv0[7]; }
                    if (sc[s2][1] > vmin0) { ins8(tv0, ti0, sc[s2][1], gc + 1); vmin0 = tv0[7]; }
                }
            }
            if (m1 > vmin1) {
                #pragma unroll
                for (int s2 = 0; s2 < 8; s2++) {
                    int gc = kofs + kb + (half * 8 + s2) * 8 + qc;
                    if (sc[s2][2] > vmin1) { ins8(tv1, ti1, sc[s2][2], gc);     vmin1 = tv1[7]; }
                    if (sc[s2][3] > vmin1) { ins8(tv1, ti1, sc[s2][3], gc + 1); vmin1 = tv1[7]; }
                }
            }
        }
        __syncthreads();
    }

    float* mv = reinterpret_cast<float*>(smc);
    int*   mi = reinterpret_cast<int*>(smc + 16384);
    #pragma unroll
    for (int t = 0; t < 8; t++) {
        mv[lr0 * 32 + slot * 8 + t] = tv0[t];
        mi[lr0 * 32 + slot * 8 + t] = ti0[t];
        mv[lr1 * 32 + slot * 8 + t] = tv1[t];
        mi[lr1 * 32 + slot * 8 + t] = ti1[t];
    }
    __syncthreads();

    if (tid < 128) {
        const float* rv = mv + tid * 32;
        const int*   ri = mi + tid * 32;
        float bv[NCQ]; int bi[NCQ];
        #pragma unroll
        for (int t = 0; t < NCQ; t++) { bv[t] = -3e38f; bi[t] = 0; }
        float vm = -3e38f;
        #pragma unroll 4
        for (int j = 0; j < 32; j++) {
            float v = rv[j];
            if (v > vm) {
                float cv = v; int ci2 = ri[j];
                #pragma unroll
                for (int t = 0; t < NCQ; t++) {
                    if (cv > bv[t]) {
                        float a = bv[t]; bv[t] = cv; cv = a;
                        int   b = bi[t]; bi[t] = ci2; ci2 = b;
                    }
                }
                vm = bv[NCQ - 1];
            }
        }
        int* outi = g_ci8 + ((size_t)blockIdx.y * NN + qbase + tid) * NCQ;
        #pragma unroll
        for (int t = 0; t < NCQ; t++) outi[t] = bi[t];
    }
}

// ---------------- K5: exact fp32 rescore of 32 candidates -> top-7 ----------------
__global__ __launch_bounds__(256) void knn_rescore_kernel()
{
    int node = (blockIdx.x * 256 + threadIdx.x) >> 5;
    int lane = threadIdx.x & 31;

    float4 hv = *reinterpret_cast<const float4*>(g_h + (size_t)node * CC + lane * 4);
    int quarter = lane >> 3, slot = lane & 7;
    int ci = g_ci8[((size_t)quarter * NN + node) * NCQ + slot];

    float myv = -3e38f;
    for (int c = 0; c < 32; c++) {
        int cj = __shfl_sync(0xffffffffu, ci, c);
        float4 hc = *reinterpret_cast<const float4*>(g_h + (size_t)cj * CC + lane * 4);
        float p = hv.x * hc.x + hv.y * hc.y + hv.z * hc.z + hv.w * hc.w;
        #pragma unroll
        for (int m = 16; m >= 1; m >>= 1) p += __shfl_xor_sync(0xffffffffu, p, m);
        if (lane == c) myv = p - g_norm[cj];
    }

    float v = myv; int idx = ci;
    #pragma unroll
    for (int t = 0; t < KNBR; t++) {
        float bv = v; int bidx = idx;
        #pragma unroll
        for (int m = 16; m >= 1; m >>= 1) {
            float ov = __shfl_xor_sync(0xffffffffu, bv, m);
            int   oi = __shfl_xor_sync(0xffffffffu, bidx, m);
            if (ov > bv || (ov == bv && oi < bidx)) { bv = ov; bidx = oi; }
        }
        if (lane == 0) g_idx[node * KNBR + t] = bidx;
        if (idx == bidx) v = -3.3e38f;
    }
}

// ---------------- K6: m1 = h @ W1 via mma.sync (bf16 4-product) — EXPERIMENT ----------------
#define PX0 0
#define PX1 17408
#define PB0 34816
#define PB1 69632
#define GCN_SMEM 104448

__global__ __launch_bounds__(256, 2) void gcn1_mma_kernel()
{
    extern __shared__ __align__(16) char smc[];
    const uint32_t sb = smem_u32(smc);
    const int tid = threadIdx.x, wid = tid >> 5, lane = tid & 31;
    const int rbase = blockIdx.x * 64;

    ld_tile64_async(sb + PX0, g_hb0 + (size_t)rbase * CC, tid);
    ld_tile64_async(sb + PX1, g_hb1 + (size_t)rbase * CC, tid);
    ld_tile_async(sb + PB0, g_w1t0, tid);
    ld_tile_async(sb + PB1, g_w1t1, tid);
    CP_COMMIT();

    const int rg = wid >> 1, cg = wid & 1;
    const int r0 = rg * 16;
    const int qrow = lane >> 2, qc = (lane & 3) * 2;
    const int gr0 = rbase + r0 + qrow, gr1 = gr0 + 8;

    const uint32_t aoff = (uint32_t)((r0 + (lane & 15)) * 272 + ((lane >> 4) & 1) * 16);
    const uint32_t boff = (uint32_t)((cg * 64 + (lane & 7) + ((lane >> 4) & 1) * 8) * 272 + ((lane >> 3) & 1) * 16);

    CP_WAIT(0);
    __syncthreads();

    float sc[8][4];
    #pragma unroll
    for (int kc = 0; kc < 8; kc++) {
        uint32_t a0[4], a1[4];
        ldsm4(a0, sb + PX0 + aoff + kc * 32);
        ldsm4(a1, sb + PX1 + aoff + kc * 32);
        #pragma unroll
        for (int n2 = 0; n2 < 4; n2++) {
            uint32_t b[4];
            ldsm4(b, sb + PB0 + (uint32_t)(n2 * 16 * 272) + boff + kc * 32);
            if (kc == 0) {
                mma16816z(sc[2 * n2],     a0, b[0], b[1]);
                mma16816z(sc[2 * n2 + 1], a0, b[2], b[3]);
            } else {
                mma16816(sc[2 * n2],     a0, b[0], b[1]);
                mma16816(sc[2 * n2 + 1], a0, b[2], b[3]);
            }
            mma16816(sc[2 * n2],     a1, b[0], b[1]);
            mma16816(sc[2 * n2 + 1], a1, b[2], b[3]);
            uint32_t b1[4];
            ldsm4(b1, sb + PB1 + (uint32_t)(n2 * 16 * 272) + boff + kc * 32);
            mma16816(sc[2 * n2],     a0, b1[0], b1[1]);
            mma16816(sc[2 * n2 + 1], a0, b1[2], b1[3]);
            mma16816(sc[2 * n2],     a1, b1[0], b1[1]);
            mma16816(sc[2 * n2 + 1], a1, b1[2], b1[3]);
        }
    }

    #pragma unroll
    for (int nt = 0; nt < 8; nt++) {
        int col = cg * 64 + nt * 8 + qc;
        *reinterpret_cast<float2*>(g_m1 + (size_t)gr0 * CC + col) = make_float2(sc[nt][0], sc[nt][1]);
        *reinterpret_cast<float2*>(g_m1 + (size_t)gr1 * CC + col) = make_float2(sc[nt][2], sc[nt][3]);
    }
}

// ---------------- K7: GCN layer-1 gather + relu ----------------
__global__ __launch_bounds__(128) void gather1(const float* __restrict__ b1)
{
    int node = blockIdx.x;
    int c    = threadIdx.x;
    float s = g_m1[node * CC + c];
    #pragma unroll
    for (int t = 0; t < KNBR; t++) {
        int nb = g_idx[node * KNBR + t];
        s += g_m1[nb * CC + c];
    }
    g_h1[node * CC + c] = fmaxf(s * 0.125f + b1[c], 0.f);
}

// ---------------- K8: m2 = h1 @ W2 ----------------
__global__ __launch_bounds__(256) void m2_kernel(const float* __restrict__ W2)
{
    int row  = blockIdx.x * 8 + (threadIdx.x >> 5);
    int lane = threadIdx.x & 31;
    float s = 0.f;
    for (int c = lane; c < CC; c += 32) s += g_h1[row * CC + c] * W2[c];
    s += __shfl_xor_sync(0xffffffffu, s, 16);
    s += __shfl_xor_sync(0xffffffffu, s, 8);
    s += __shfl_xor_sync(0xffffffffu, s, 4);
    s += __shfl_xor_sync(0xffffffffu, s, 2);
    s += __shfl_xor_sync(0xffffffffu, s, 1);
    if (lane == 0) g_m2[row] = s;
}

// ---------------- K9: GCN layer-2 gather -> output ----------------
__global__ __launch_bounds__(256) void out_kernel(const float* __restrict__ b2,
                                                  float* __restrict__ out)
{
    int n = blockIdx.x * 256 + threadIdx.x;
    float s = g_m2[n];
    #pragma unroll
    for (int t = 0; t < KNBR; t++) s += g_m2[g_idx[n * KNBR + t]];
    out[n] = s * 0.125f + b2[0];
}

// ---------------- launch ----------------
extern "C" void kernel_launch(void* const* d_in, const int* in_sizes, int n_in,
                              void* d_out, int out_size)
{
    const float* x   = (const float*)d_in[0];
    const float* Wq  = (const float*)d_in[1];
    const float* bq  = (const float*)d_in[2];
    const float* Wk  = (const float*)d_in[3];
    const float* bk  = (const float*)d_in[4];
    const float* Wv  = (const float*)d_in[5];
    const float* bv  = (const float*)d_in[6];
    const float* Wsk = (const float*)d_in[7];
    const float* bsk = (const float*)d_in[8];
    const float* W1  = (const float*)d_in[9];
    const float* b1  = (const float*)d_in[10];
    const float* W2  = (const float*)d_in[11];
    const float* b2  = (const float*)d_in[12];
    float* out = (float*)d_out;

    cudaFuncSetAttribute(attn_mma_kernel, cudaFuncAttributeMaxDynamicSharedMemorySize, ATTN_SMEM);
    cudaFuncSetAttribute(knn_mma_kernel,  cudaFuncAttributeMaxDynamicSharedMemorySize, KNN_SMEM);
    cudaFuncSetAttribute(gcn1_mma_kernel, cudaFuncAttributeMaxDynamicSharedMemorySize, GCN_SMEM);

    split_w1_kernel<<<64, 256>>>(W1);
    proj_kernel<<<NN / 32, 256>>>(x, Wq, bq, Wk, bk, Wv, bv, Wsk, bsk);
    attn_mma_kernel<<<dim3(NN / 128, 2), 256, ATTN_SMEM>>>();
    combine_norm_kernel<<<NN / 8, 256>>>();
    knn_mma_kernel<<<dim3(NN / 128, 4), 256, KNN_SMEM>>>();
    knn_rescore_kernel<<<NN / 8, 256>>>();
    gcn1_mma_kernel<<<NN / 64, 256, GCN_SMEM>>>();
    gather1<<<NN, CC>>>(b1);
    m2_kernel<<<NN / 8, 256>>>(W2);
    out_kernel<<<NN / 256, 256>>>(b2, out);
}

// round 16
// speedup vs baseline: 1.1387x; 1.0414x over previous
#include <cuda_runtime.h>
#include <cuda_bf16.h>
#include <cuda_fp16.h>
#include <cstdint>

#define NN    8192
#define CC    128
#define KNBR  7
#define HALFN 4096
#define QUARTN 2048
#define NTH   (HALFN / 128)
#define NTQ   (QUARTN / 128)
#define NCQ   8

typedef unsigned long long ull;

// ---------------- device scratch ----------------
__device__ float g_skip[NN * CC];
__device__ float g_h[NN * CC];
__device__ float g_acc[2 * NN * CC];
__device__ float g_l[2 * NN];
__device__ float g_norm[NN];
__device__ int   g_ci8[4 * NN * NCQ];
__device__ int   g_idx[NN * KNBR];
__device__ float g_m1[NN * CC];
__device__ float g_h1[NN * CC];
__device__ float g_m2[NN];
__device__ __nv_bfloat16 g_qb0[NN * CC], g_qb1[NN * CC];
__device__ __nv_bfloat16 g_kb0[NN * CC], g_kb1[NN * CC];
__device__ __half        g_vh[NN * CC];
__device__ __nv_bfloat16 g_hb0[NN * CC], g_hb1[NN * CC];
__device__ __nv_bfloat16 g_wt0[4 * CC * CC], g_wt1[4 * CC * CC]; // Wq,Wk,Wv,W1 ^T splits

// ---------------- packed fp32x2 (SIMT skip GEMM) ----------------
__device__ __forceinline__ ull ffma2(ull a, ull b, ull c) {
    ull d;
    asm("fma.rn.f32x2 %0, %1, %2, %3;" : "=l"(d) : "l"(a), "l"(b), "l"(c));
    return d;
}
__device__ __forceinline__ ull dup2(float x) {
    ull d;
    asm("mov.b64 %0, {%1, %1};" : "=l"(d) : "f"(x));
    return d;
}
__device__ __forceinline__ float2 upk(ull v) {
    float2 r;
    asm("mov.b64 {%0, %1}, %2;" : "=f"(r.x), "=f"(r.y) : "l"(v));
    return r;
}

// ---------------- mma / ldmatrix / cp.async helpers ----------------
__device__ __forceinline__ uint32_t smem_u32(const void* p) {
    uint32_t a;
    asm("{ .reg .u64 t; cvta.to.shared.u64 t, %1; cvt.u32.u64 %0, t; }" : "=r"(a) : "l"(p));
    return a;
}
__device__ __forceinline__ void ldsm4(uint32_t* r, uint32_t a) {
    asm volatile("ldmatrix.sync.aligned.m8n8.x4.shared.b16 {%0,%1,%2,%3}, [%4];"
                 : "=r"(r[0]), "=r"(r[1]), "=r"(r[2]), "=r"(r[3]) : "r"(a));
}
__device__ __forceinline__ void ldsm4t(uint32_t* r, uint32_t a) {
    asm volatile("ldmatrix.sync.aligned.m8n8.x4.trans.shared.b16 {%0,%1,%2,%3}, [%4];"
                 : "=r"(r[0]), "=r"(r[1]), "=r"(r[2]), "=r"(r[3]) : "r"(a));
}
__device__ __forceinline__ void mma16816(float* c, const uint32_t* a, uint32_t b0, uint32_t b1) {
    asm volatile(
        "mma.sync.aligned.m16n8k16.row.col.f32.bf16.bf16.f32 "
        "{%0,%1,%2,%3}, {%4,%5,%6,%7}, {%8,%9}, {%0,%1,%2,%3};"
        : "+f"(c[0]), "+f"(c[1]), "+f"(c[2]), "+f"(c[3])
        : "r"(a[0]), "r"(a[1]), "r"(a[2]), "r"(a[3]), "r"(b0), "r"(b1));
}
__device__ __forceinline__ void mma16816z(float* d, const uint32_t* a, uint32_t b0, uint32_t b1) {
    asm volatile(
        "mma.sync.aligned.m16n8k16.row.col.f32.bf16.bf16.f32 "
        "{%0,%1,%2,%3}, {%4,%5,%6,%7}, {%8,%9}, {%10,%10,%10,%10};"
        : "=f"(d[0]), "=f"(d[1]), "=f"(d[2]), "=f"(d[3])
        : "r"(a[0]), "r"(a[1]), "r"(a[2]), "r"(a[3]), "r"(b0), "r"(b1), "f"(0.f));
}
__device__ __forceinline__ void mma16816h(float* c, const uint32_t* a, uint32_t b0, uint32_t b1) {
    asm volatile(
        "mma.sync.aligned.m16n8k16.row.col.f32.f16.f16.f32 "
        "{%0,%1,%2,%3}, {%4,%5,%6,%7}, {%8,%9}, {%0,%1,%2,%3};"
        : "+f"(c[0]), "+f"(c[1]), "+f"(c[2]), "+f"(c[3])
        : "r"(a[0]), "r"(a[1]), "r"(a[2]), "r"(a[3]), "r"(b0), "r"(b1));
}
#define CP_COMMIT() asm volatile("cp.async.commit_group;" ::: "memory")
#define CP_WAIT(n)  asm volatile("cp.async.wait_group %0;" :: "n"(n) : "memory")

__device__ __forceinline__ uint32_t pack_bf(float x, float y) {
    __nv_bfloat162 t = __floats2bfloat162_rn(x, y);
    return *reinterpret_cast<uint32_t*>(&t);
}
__device__ __forceinline__ uint32_t pack_h(float x, float y) {
    __half2 t = __floats2half2_rn(x, y);
    return *reinterpret_cast<uint32_t*>(&t);
}
__device__ __forceinline__ void split_pair(float x, float y, uint32_t& p0, uint32_t& p1) {
    __nv_bfloat16 bx = __float2bfloat16_rn(x), by = __float2bfloat16_rn(y);
    __nv_bfloat162 t; t.x = bx; t.y = by;
    p0 = *reinterpret_cast<uint32_t*>(&t);
    p1 = pack_bf(x - __bfloat162float(bx), y - __bfloat162float(by));
}
__device__ __forceinline__ void split_pair_h(float x, float y, uint32_t& p0, uint32_t& p1) {
    __half hx = __float2half_rn(x), hy = __float2half_rn(y);
    __half2 t; t.x = hx; t.y = hy;
    p0 = *reinterpret_cast<uint32_t*>(&t);
    p1 = pack_h(x - __half2float(hx), y - __half2float(hy));
}
// async 128x128 16-bit tile -> smem rows of 272B
__device__ __forceinline__ void ld_tile_async(uint32_t dst, const void* __restrict__ srcv, int tid) {
    const char* src = reinterpret_cast<const char*>(srcv);
    #pragma unroll
    for (int i = 0; i < 8; i++) {
        int idx = tid + i * 256;
        int row = idx >> 4, ch = idx & 15;
        asm volatile("cp.async.cg.shared.global [%0], [%1], 16;" ::
            "r"(dst + (uint32_t)(row * 272 + ch * 16)), "l"(src + (size_t)row * CC * 2 + ch * 16) : "memory");
    }
}
// async 64x128 16-bit tile -> smem rows of 272B
__device__ __forceinline__ void ld_tile64_async(uint32_t dst, const void* __restrict__ srcv, int tid) {
    const char* src = reinterpret_cast<const char*>(srcv);
    #pragma unroll
    for (int i = 0; i < 4; i++) {
        int idx = tid + i * 256;
        int row = idx >> 4, ch = idx & 15;
        asm volatile("cp.async.cg.shared.global [%0], [%1], 16;" ::
            "r"(dst + (uint32_t)(row * 272 + ch * 16)), "l"(src + (size_t)row * CC * 2 + ch * 16) : "memory");
    }
}
__device__ __forceinline__ void ins8(float* tv, int* ti, float v, int idx) {
    #pragma unroll
    for (int t = 0; t < 8; t++) {
        if (v > tv[t]) {
            float a = tv[t]; tv[t] = v; v = a;
            int   b = ti[t]; ti[t] = idx; idx = b;
        }
    }
}

// ---------------- K0: transpose + bf16-split Wq,Wk,Wv,W1 ----------------
__global__ __launch_bounds__(256) void split_w_kernel(
    const float* __restrict__ Wq, const float* __restrict__ Wk,
    const float* __restrict__ Wv, const float* __restrict__ W1)
{
    int i = blockIdx.x * 256 + threadIdx.x;
    int m = blockIdx.y;
    const float* W = (m == 0) ? Wq : (m == 1) ? Wk : (m == 2) ? Wv : W1;
    int k = i >> 7, n = i & 127;
    float v = W[i];
    __nv_bfloat16 b0 = __float2bfloat16_rn(v);
    g_wt0[m * CC * CC + n * CC + k] = b0;
    g_wt1[m * CC * CC + n * CC + k] = __float2bfloat16_rn(v - __bfloat162float(b0));
}

// ---------------- K1a: skip = x @ Wskip + bskip (SIMT fp32 — h-exact path) ----------------
__global__ __launch_bounds__(256) void skip_kernel(
    const float* __restrict__ x,
    const float* __restrict__ Ws, const float* __restrict__ bs)
{
    __shared__ float xs[32 * 129];
    const int tid = threadIdx.x;
    const int r0  = blockIdx.x * 32;

    for (int i = tid; i < 32 * CC; i += 256) {
        int r = i >> 7, c = i & 127;
        xs[r * 129 + c] = x[(r0 + r) * CC + c];
    }
    __syncthreads();

    const int ri = (tid >> 5) * 4;
    const int c0 = (tid & 31) * 4;

    ull acc[4][2];
    #pragma unroll
    for (int i = 0; i < 4; i++) { acc[i][0] = 0ULL; acc[i][1] = 0ULL; }

    #pragma unroll 4
    for (int k2 = 0; k2 < CC; k2++) {
        ulonglong2 wp = *reinterpret_cast<const ulonglong2*>(Ws + k2 * CC + c0);
        #pragma unroll
        for (int dr = 0; dr < 4; dr++) {
            ull x2 = dup2(xs[(ri + dr) * 129 + k2]);
            acc[dr][0] = ffma2(x2, wp.x, acc[dr][0]);
            acc[dr][1] = ffma2(x2, wp.y, acc[dr][1]);
        }
    }
    float4 bb = *reinterpret_cast<const float4*>(bs + c0);
    #pragma unroll
    for (int dr = 0; dr < 4; dr++) {
        float2 a0 = upk(acc[dr][0]), a1 = upk(acc[dr][1]);
        float4 o;
        o.x = a0.x + bb.x; o.y = a0.y + bb.y;
        o.z = a1.x + bb.z; o.w = a1.y + bb.w;
        *reinterpret_cast<float4*>(g_skip + (r0 + ri + dr) * CC + c0) = o;
    }
}

// ---------------- K1b: q/k/v via mma.sync (bf16 4-product; smooth paths only) ----------------
#define PX0 0
#define PX1 17408
#define PB0 34816
#define PB1 69632
#define PROJ_SMEM 104448

__global__ __launch_bounds__(256, 2) void projqkv_mma_kernel(
    const float* __restrict__ x,
    const float* __restrict__ bq, const float* __restrict__ bk,
    const float* __restrict__ bv)
{
    extern __shared__ __align__(16) char smc[];
    const uint32_t sb = smem_u32(smc);
    const int tid = threadIdx.x, wid = tid >> 5, lane = tid & 31;
    const int rbase = blockIdx.x * 64;
    const float SCALE = 0.08838834764831843f;

    ld_tile_async(sb + PB0, g_wt0, tid);
    ld_tile_async(sb + PB1, g_wt1, tid);
    CP_COMMIT();

    // x split -> smem (64 rows)
    #pragma unroll
    for (int i = 0; i < 8; i++) {
        int idx = tid + i * 256;
        int row = idx >> 5, c4 = (idx & 31) * 4;
        float4 v = *reinterpret_cast<const float4*>(x + (size_t)(rbase + row) * CC + c4);
        uint32_t lo0, hi0, lo1, hi1;
        split_pair(v.x, v.y, lo0, hi0);
        split_pair(v.z, v.w, lo1, hi1);
        uint2 u0 = {lo0, lo1};
        uint2 u1 = {hi0, hi1};
        *reinterpret_cast<uint2*>(smc + PX0 + row * 272 + c4 * 2) = u0;
        *reinterpret_cast<uint2*>(smc + PX1 + row * 272 + c4 * 2) = u1;
    }

    const int rg = wid >> 1, cg = wid & 1;
    const int r0 = rg * 16;
    const int qrow = lane >> 2, qc = (lane & 3) * 2;
    const int gr0 = rbase + r0 + qrow, gr1 = gr0 + 8;

    const uint32_t aoff = (uint32_t)((r0 + (lane & 15)) * 272 + ((lane >> 4) & 1) * 16);
    const uint32_t boff = (uint32_t)((cg * 64 + (lane & 7) + ((lane >> 4) & 1) * 8) * 272 + ((lane >> 3) & 1) * 16);

    const float* bt[3] = {bq, bk, bv};

    for (int w = 0; w < 3; w++) {
        CP_WAIT(0);
        __syncthreads();

        float sc[8][4];
        #pragma unroll
        for (int kc = 0; kc < 8; kc++) {
            uint32_t a0[4], a1[4];
            ldsm4(a0, sb + PX0 + aoff + kc * 32);
            ldsm4(a1, sb + PX1 + aoff + kc * 32);
            #pragma unroll
            for (int n2 = 0; n2 < 4; n2++) {
                uint32_t b[4];
                ldsm4(b, sb + PB0 + (uint32_t)(n2 * 16 * 272) + boff + kc * 32);
                if (kc == 0) {
                    mma16816z(sc[2 * n2],     a0, b[0], b[1]);
                    mma16816z(sc[2 * n2 + 1], a0, b[2], b[3]);
                } else {
                    mma16816(sc[2 * n2],     a0, b[0], b[1]);
                    mma16816(sc[2 * n2 + 1], a0, b[2], b[3]);
                }
                mma16816(sc[2 * n2],     a1, b[0], b[1]);
                mma16816(sc[2 * n2 + 1], a1, b[2], b[3]);
                uint32_t b1[4];
                ldsm4(b1, sb + PB1 + (uint32_t)(n2 * 16 * 272) + boff + kc * 32);
                mma16816(sc[2 * n2],     a0, b1[0], b1[1]);
                mma16816(sc[2 * n2 + 1], a0, b1[2], b1[3]);
                mma16816(sc[2 * n2],     a1, b1[0], b1[1]);
                mma16816(sc[2 * n2 + 1], a1, b1[2], b1[3]);
            }
        }
        __syncthreads();
        if (w < 2) {
            ld_tile_async(sb + PB0, g_wt0 + (size_t)(w + 1) * CC * CC, tid);
            ld_tile_async(sb + PB1, g_wt1 + (size_t)(w + 1) * CC * CC, tid);
            CP_COMMIT();
        }

        #pragma unroll
        for (int nt = 0; nt < 8; nt++) {
            int col = cg * 64 + nt * 8 + qc;
            float2 bb = *reinterpret_cast<const float2*>(bt[w] + col);
            float v00 = sc[nt][0] + bb.x, v01 = sc[nt][1] + bb.y;   // row gr0
            float v10 = sc[nt][2] + bb.x, v11 = sc[nt][3] + bb.y;   // row gr1
            if (w == 2) {
                *reinterpret_cast<uint32_t*>(g_vh + (size_t)gr0 * CC + col) = pack_h(v00, v01);
                *reinterpret_cast<uint32_t*>(g_vh + (size_t)gr1 * CC + col) = pack_h(v10, v11);
            } else {
                float s = (w == 0) ? SCALE : 1.f;
                __nv_bfloat16* d0 = (w == 0) ? g_qb0 : g_kb0;
                __nv_bfloat16* d1 = (w == 0) ? g_qb1 : g_kb1;
                uint32_t lo, hi;
                split_pair(v00 * s, v01 * s, lo, hi);
                *reinterpret_cast<uint32_t*>(d0 + (size_t)gr0 * CC + col) = lo;
                *reinterpret_cast<uint32_t*>(d1 + (size_t)gr0 * CC + col) = hi;
                split_pair(v10 * s, v11 * s, lo, hi);
                *reinterpret_cast<uint32_t*>(d0 + (size_t)gr1 * CC + col) = lo;
                *reinterpret_cast<uint32_t*>(d1 + (size_t)gr1 * CC + col) = hi;
            }
        }
    }
}

// ---------------- K2: flash attention (R10-winning version, verbatim) ----------------
#define AQ0 0
#define AQ1 34816
#define AK0 69632
#define AK1 104448
#define AV0 139264
#define ATTN_SMEM 174080

__global__ __launch_bounds__(256, 1) void attn_mma_kernel()
{
    extern __shared__ __align__(16) char smc[];
    const uint32_t sb = smem_u32(smc);
    const int tid  = threadIdx.x, wid = tid >> 5, lane = tid & 31;
    const int qbase = blockIdx.x * 128;
    const int kofs  = blockIdx.y * HALFN;

    ld_tile_async(sb + AQ0, g_qb0 + (size_t)qbase * CC, tid);
    ld_tile_async(sb + AQ1, g_qb1 + (size_t)qbase * CC, tid);
    CP_COMMIT();
    ld_tile_async(sb + AK0, g_kb0 + (size_t)kofs * CC, tid);
    ld_tile_async(sb + AK1, g_kb1 + (size_t)kofs * CC, tid);
    CP_COMMIT();
    ld_tile_async(sb + AV0, g_vh + (size_t)kofs * CC, tid);
    CP_COMMIT();

    const int r0   = wid * 16;
    const int qrow = lane >> 2, qc = (lane & 3) * 2;
    const int gr0  = qbase + r0 + qrow, gr1 = gr0 + 8;

    const uint32_t aoff = (uint32_t)((r0 + (lane & 15)) * 272 + ((lane >> 4) & 1) * 16);
    const uint32_t boff = (uint32_t)(((lane & 7) + ((lane >> 4) & 1) * 8) * 272 + ((lane >> 3) & 1) * 16);
    const uint32_t voff = (uint32_t)(((lane & 7) + ((lane >> 3) & 1) * 8) * 272 + ((lane >> 4) & 1) * 16);

    float pv[16][4];
    #pragma unroll
    for (int i = 0; i < 16; i++)
        #pragma unroll
        for (int j = 0; j < 4; j++) pv[i][j] = 0.f;
    float l0 = 0.f, l1 = 0.f;

    CP_WAIT(1);
    __syncthreads();

    for (int t = 0; t < NTH; t++) {
        const int kb = t * 128;
        const bool more = (t + 1 < NTH);

        float sc[16][4];

        #pragma unroll
        for (int kc = 0; kc < 8; kc++) {
            uint32_t a0[4], a1[4];
            ldsm4(a0, sb + AQ0 + aoff + kc * 32);
            ldsm4(a1, sb + AQ1 + aoff + kc * 32);
            if (kc == 0) {
                #pragma unroll
                for (int nt2 = 0; nt2 < 8; nt2++) {
                    uint32_t b[4];
                    ldsm4(b, sb + AK0 + (uint32_t)(nt2 * 16 * 272) + boff);
                    mma16816z(sc[2 * nt2],     a0, b[0], b[1]);
                    mma16816z(sc[2 * nt2 + 1], a0, b[2], b[3]);
                    mma16816(sc[2 * nt2],     a1, b[0], b[1]);
                    mma16816(sc[2 * nt2 + 1], a1, b[2], b[3]);
                }
            } else {
                #pragma unroll
                for (int nt2 = 0; nt2 < 8; nt2++) {
                    uint32_t b[4];
                    ldsm4(b, sb + AK0 + (uint32_t)(nt2 * 16 * 272) + boff + kc * 32);
                    mma16816(sc[2 * nt2],     a0, b[0], b[1]);
                    mma16816(sc[2 * nt2 + 1], a0, b[2], b[3]);
                    mma16816(sc[2 * nt2],     a1, b[0], b[1]);
                    mma16816(sc[2 * nt2 + 1], a1, b[2], b[3]);
                }
            }
            #pragma unroll
            for (int nt2 = 0; nt2 < 8; nt2++) {
                uint32_t b[4];
                ldsm4(b, sb + AK1 + (uint32_t)(nt2 * 16 * 272) + boff + kc * 32);
                mma16816(sc[2 * nt2],     a0, b[0], b[1]);
                mma16816(sc[2 * nt2 + 1], a0, b[2], b[3]);
            }
        }

        float rs0 = 0.f, rs1 = 0.f;
        if (kofs + kb == qbase) {
            #pragma unroll
            for (int nt = 0; nt < 16; nt++) {
                int gc = kofs + kb + nt * 8 + qc;
                float e0 = (gr0 == gc)     ? 0.f : __expf(sc[nt][0]);
                float e1 = (gr0 == gc + 1) ? 0.f : __expf(sc[nt][1]);
                float e2 = (gr1 == gc)     ? 0.f : __expf(sc[nt][2]);
                float e3 = (gr1 == gc + 1) ? 0.f : __expf(sc[nt][3]);
                sc[nt][0] = e0; sc[nt][1] = e1; sc[nt][2] = e2; sc[nt][3] = e3;
                rs0 += e0 + e1; rs1 += e2 + e3;
            }
        } else {
            #pragma unroll
            for (int nt = 0; nt < 16; nt++) {
                float e0 = __expf(sc[nt][0]);
                float e1 = __expf(sc[nt][1]);
                float e2 = __expf(sc[nt][2]);
                float e3 = __expf(sc[nt][3]);
                sc[nt][0] = e0; sc[nt][1] = e1; sc[nt][2] = e2; sc[nt][3] = e3;
                rs0 += e0 + e1; rs1 += e2 + e3;
            }
        }
        rs0 += __shfl_xor_sync(0xffffffffu, rs0, 1);
        rs0 += __shfl_xor_sync(0xffffffffu, rs0, 2);
        rs1 += __shfl_xor_sync(0xffffffffu, rs1, 1);
        rs1 += __shfl_xor_sync(0xffffffffu, rs1, 2);
        l0 += rs0; l1 += rs1;

        CP_WAIT(0);
        __syncthreads();

        if (more) {
            ld_tile_async(sb + AK0, g_kb0 + (size_t)(kofs + kb + 128) * CC, tid);
            ld_tile_async(sb + AK1, g_kb1 + (size_t)(kofs + kb + 128) * CC, tid);
            CP_COMMIT();
        }

        #pragma unroll
        for (int kc = 0; kc < 8; kc++) {
            uint32_t p0[4], p1[4];
            split_pair_h(sc[2 * kc][0],     sc[2 * kc][1],     p0[0], p1[0]);
            split_pair_h(sc[2 * kc][2],     sc[2 * kc][3],     p0[1], p1[1]);
            split_pair_h(sc[2 * kc + 1][0], sc[2 * kc + 1][1], p0[2], p1[2]);
            split_pair_h(sc[2 * kc + 1][2], sc[2 * kc + 1][3], p0[3], p1[3]);
            #pragma unroll
            for (int nt2 = 0; nt2 < 8; nt2++) {
                uint32_t vf[4];
                ldsm4t(vf, sb + AV0 + (uint32_t)(kc * 16 * 272) + voff + nt2 * 32);
                mma16816h(pv[2 * nt2],     p0, vf[0], vf[1]);
                mma16816h(pv[2 * nt2 + 1], p0, vf[2], vf[3]);
                mma16816h(pv[2 * nt2],     p1, vf[0], vf[1]);
                mma16816h(pv[2 * nt2 + 1], p1, vf[2], vf[3]);
            }
        }
        __syncthreads();

        if (more) {
            ld_tile_async(sb + AV0, g_vh + (size_t)(kofs + kb + 128) * CC, tid);
            CP_COMMIT();
            CP_WAIT(1);
            __syncthreads();
        }
    }

    float* aout = g_acc + (size_t)blockIdx.y * NN * CC;
    #pragma unroll
    for (int nt = 0; nt < 16; nt++) {
        int c = nt * 8 + qc;
        *reinterpret_cast<float2*>(aout + (size_t)gr0 * CC + c) = make_float2(pv[nt][0], pv[nt][1]);
        *reinterpret_cast<float2*>(aout + (size_t)gr1 * CC + c) = make_float2(pv[nt][2], pv[nt][3]);
    }
    if ((lane & 3) == 0) {
        g_l[blockIdx.y * NN + gr0] = l0;
        g_l[blockIdx.y * NN + gr1] = l1;
    }
}

// ---------------- K3: fused combine + norm + bf16 2-split of h ----------------
__global__ __launch_bounds__(256) void combine_norm_kernel()
{
    int row  = blockIdx.x * 8 + (threadIdx.x >> 5);
    int lane = threadIdx.x & 31;
    size_t base = (size_t)row * CC + lane * 4;

    float inv = __fdividef(1.f, g_l[row] + g_l[NN + row]);
    float4 a0 = *reinterpret_cast<const float4*>(g_acc + base);
    float4 a1 = *reinterpret_cast<const float4*>(g_acc + (size_t)NN * CC + base);
    float4 sk = *reinterpret_cast<const float4*>(g_skip + base);

    float4 h;
    h.x = (a0.x + a1.x) * inv + sk.x;
    h.y = (a0.y + a1.y) * inv + sk.y;
    h.z = (a0.z + a1.z) * inv + sk.z;
    h.w = (a0.w + a1.w) * inv + sk.w;
    *reinterpret_cast<float4*>(g_h + base) = h;

    uint32_t lo0, hi0, lo1, hi1;
    split_pair(h.x, h.y, lo0, hi0);
    split_pair(h.z, h.w, lo1, hi1);
    uint2 u0 = {lo0, lo1};
    uint2 u1 = {hi0, hi1};
    *reinterpret_cast<uint2*>(g_hb0 + base) = u0;
    *reinterpret_cast<uint2*>(g_hb1 + base) = u1;

    float s = h.x * h.x + h.y * h.y + h.z * h.z + h.w * h.w;
    s += __shfl_xor_sync(0xffffffffu, s, 16);
    s += __shfl_xor_sync(0xffffffffu, s, 8);
    s += __shfl_xor_sync(0xffffffffu, s, 4);
    s += __shfl_xor_sync(0xffffffffu, s, 2);
    s += __shfl_xor_sync(0xffffffffu, s, 1);
    if (lane == 0) g_norm[row] = 0.5f * s;
}

// ---------------- K4: kNN candidates — 4 key quarters, 2 CTAs/SM ----------------
#define KQ0 0
#define KK0 34816
#define KNR 69632
#define KNN_SMEM 70144

__global__ __launch_bounds__(256, 2) void knn_mma_kernel()
{
    extern __shared__ __align__(16) char smc[];
    const uint32_t sb = smem_u32(smc);
    float* nr_s = reinterpret_cast<float*>(smc + KNR);

    const int tid  = threadIdx.x, wid = tid >> 5, lane = tid & 31;
    const int qbase = blockIdx.x * 128;
    const int kofs  = blockIdx.y * QUARTN;

    ld_tile_async(sb + KQ0, g_hb0 + (size_t)qbase * CC, tid);
    CP_COMMIT();

    const int r0   = wid * 16;
    const int qrow = lane >> 2, qc = (lane & 3) * 2;
    const int gr0  = qbase + r0 + qrow, gr1 = gr0 + 8;
    const int lr0  = r0 + qrow, lr1 = lr0 + 8;
    const int slot = lane & 3;

    const uint32_t aoff = (uint32_t)((r0 + (lane & 15)) * 272 + ((lane >> 4) & 1) * 16);
    const uint32_t boff = (uint32_t)(((lane & 7) + ((lane >> 4) & 1) * 8) * 272 + ((lane >> 3) & 1) * 16);

    float tv0[8], tv1[8];
    int   ti0[8], ti1[8];
    #pragma unroll
    for (int t = 0; t < 8; t++) { tv0[t] = -3e38f; tv1[t] = -3e38f; ti0[t] = 0; ti1[t] = 0; }
    float vmin0 = -3e38f, vmin1 = -3e38f;

    for (int t = 0; t < NTQ; t++) {
        const int kb = t * 128;
        ld_tile_async(sb + KK0, g_hb0 + (size_t)(kofs + kb) * CC, tid);
        CP_COMMIT();
        if (tid < 128) nr_s[tid] = g_norm[kofs + kb + tid];
        CP_WAIT(0);
        __syncthreads();

        const bool hasdiag = (kofs + kb == qbase);

        #pragma unroll
        for (int half = 0; half < 2; half++) {
            float sc[8][4];

            #pragma unroll
            for (int kc = 0; kc < 8; kc++) {
                uint32_t a[4];
                ldsm4(a, sb + KQ0 + aoff + kc * 32);
                if (kc == 0) {
                    #pragma unroll
                    for (int n2 = 0; n2 < 4; n2++) {
                        uint32_t b[4];
                        ldsm4(b, sb + KK0 + (uint32_t)((half * 4 + n2) * 16 * 272) + boff);
                        mma16816z(sc[2 * n2],     a, b[0], b[1]);
                        mma16816z(sc[2 * n2 + 1], a, b[2], b[3]);
                    }
                } else {
                    #pragma unroll
                    for (int n2 = 0; n2 < 4; n2++) {
                        uint32_t b[4];
                        ldsm4(b, sb + KK0 + (uint32_t)((half * 4 + n2) * 16 * 272) + boff + kc * 32);
                        mma16816(sc[2 * n2],     a, b[0], b[1]);
                        mma16816(sc[2 * n2 + 1], a, b[2], b[3]);
                    }
                }
            }

            #pragma unroll
            for (int s2 = 0; s2 < 8; s2++) {
                int c = (half * 8 + s2) * 8 + qc;
                float nr0 = nr_s[c], nr1 = nr_s[c + 1];
                sc[s2][0] -= nr0;
                sc[s2][1] -= nr1;
                sc[s2][2] -= nr0;
                sc[s2][3] -= nr1;
            }
            if (hasdiag) {
                #pragma unroll
                for (int s2 = 0; s2 < 8; s2++) {
                    int gc = kofs + kb + (half * 8 + s2) * 8 + qc;
                    if (gr0 == gc)     sc[s2][0] = -3e38f;
                    if (gr0 == gc + 1) sc[s2][1] = -3e38f;
                    if (gr1 == gc)     sc[s2][2] = -3e38f;
                    if (gr1 == gc + 1) sc[s2][3] = -3e38f;
                }
            }
            float m0 = -3e38f, m1 = -3e38f;
            #pragma unroll
            for (int s2 = 0; s2 < 8; s2++) {
                m0 = fmaxf(m0, fmaxf(sc[s2][0], sc[s2][1]));
                m1 = fmaxf(m1, fmaxf(sc[s2][2], sc[s2][3]));
            }
            if (m0 > vmin0) {
                #pragma unroll
                for (int s2 = 0; s2 < 8; s2++) {
                    int gc = kofs + kb + (half * 8 + s2) * 8 + qc;
                    if (sc[s2][0] > vmin0) { ins8(tv0, ti0, sc[s2][0], gc);     vmin0 = tv0[7]; }
                    if (sc[s2][1] > vmin0) { ins8(tv0, ti0, sc[s2][1], gc + 1); vmin0 = tv0[7]; }
                }
            }
            if (m1 > vmin1) {
                #pragma unroll
                for (int s2 = 0; s2 < 8; s2++) {
                    int gc = kofs + kb + (half * 8 + s2) * 8 + qc;
                    if (sc[s2][2] > vmin1) { ins8(tv1, ti1, sc[s2][2], gc);     vmin1 = tv1[7]; }
                    if (sc[s2][3] > vmin1) { ins8(tv1, ti1, sc[s2][3], gc + 1); vmin1 = tv1[7]; }
                }
            }
        }
        __syncthreads();
    }

    float* mv = reinterpret_cast<float*>(smc);
    int*   mi = reinterpret_cast<int*>(smc + 16384);
    #pragma unroll
    for (int t = 0; t < 8; t++) {
        mv[lr0 * 32 + slot * 8 + t] = tv0[t];
        mi[lr0 * 32 + slot * 8 + t] = ti0[t];
        mv[lr1 * 32 + slot * 8 + t] = tv1[t];
        mi[lr1 * 32 + slot * 8 + t] = ti1[t];
    }
    __syncthreads();

    if (tid < 128) {
        const float* rv = mv + tid * 32;
        const int*   ri = mi + tid * 32;
        float bv[NCQ]; int bi[NCQ];
        #pragma unroll
        for (int t = 0; t < NCQ; t++) { bv[t] = -3e38f; bi[t] = 0; }
        float vm = -3e38f;
        #pragma unroll 4
        for (int j = 0; j < 32; j++) {
            float v = rv[j];
            if (v > vm) {
                float cv = v; int ci2 = ri[j];
                #pragma unroll
                for (int t = 0; t < NCQ; t++) {
                    if (cv > bv[t]) {
                        float a = bv[t]; bv[t] = cv; cv = a;
                        int   b = bi[t]; bi[t] = ci2; ci2 = b;
                    }
                }
                vm = bv[NCQ - 1];
            }
        }
        int* outi = g_ci8 + ((size_t)blockIdx.y * NN + qbase + tid) * NCQ;
        #pragma unroll
        for (int t = 0; t < NCQ; t++) outi[t] = bi[t];
    }
}

// ---------------- K5: exact fp32 rescore of 32 candidates -> top-7 ----------------
__global__ __launch_bounds__(256) void knn_rescore_kernel()
{
    int node = (blockIdx.x * 256 + threadIdx.x) >> 5;
    int lane = threadIdx.x & 31;

    float4 hv = *reinterpret_cast<const float4*>(g_h + (size_t)node * CC + lane * 4);
    int quarter = lane >> 3, slot = lane & 7;
    int ci = g_ci8[((size_t)quarter * NN + node) * NCQ + slot];

    float myv = -3e38f;
    for (int c = 0; c < 32; c++) {
        int cj = __shfl_sync(0xffffffffu, ci, c);
        float4 hc = *reinterpret_cast<const float4*>(g_h + (size_t)cj * CC + lane * 4);
        float p = hv.x * hc.x + hv.y * hc.y + hv.z * hc.z + hv.w * hc.w;
        #pragma unroll
        for (int m = 16; m >= 1; m >>= 1) p += __shfl_xor_sync(0xffffffffu, p, m);
        if (lane == c) myv = p - g_norm[cj];
    }

    float v = myv; int idx = ci;
    #pragma unroll
    for (int t = 0; t < KNBR; t++) {
        float bv = v; int bidx = idx;
        #pragma unroll
        for (int m = 16; m >= 1; m >>= 1) {
            float ov = __shfl_xor_sync(0xffffffffu, bv, m);
            int   oi = __shfl_xor_sync(0xffffffffu, bidx, m);
            if (ov > bv || (ov == bv && oi < bidx)) { bv = ov; bidx = oi; }
        }
        if (lane == 0) g_idx[node * KNBR + t] = bidx;
        if (idx == bidx) v = -3.3e38f;
    }
}

// ---------------- K6: m1 = h @ W1 via mma.sync (bf16 4-product, proven) ----------------
__global__ __launch_bounds__(256, 2) void gcn1_mma_kernel()
{
    extern __shared__ __align__(16) char smc[];
    const uint32_t sb = smem_u32(smc);
    const int tid = threadIdx.x, wid = tid >> 5, lane = tid & 31;
    const int rbase = blockIdx.x * 64;

    ld_tile64_async(sb + PX0, g_hb0 + (size_t)rbase * CC, tid);
    ld_tile64_async(sb + PX1, g_hb1 + (size_t)rbase * CC, tid);
    ld_tile_async(sb + PB0, g_wt0 + (size_t)3 * CC * CC, tid);
    ld_tile_async(sb + PB1, g_wt1 + (size_t)3 * CC * CC, tid);
    CP_COMMIT();

    const int rg = wid >> 1, cg = wid & 1;
    const int r0 = rg * 16;
    const int qrow = lane >> 2, qc = (lane & 3) * 2;
    const int gr0 = rbase + r0 + qrow, gr1 = gr0 + 8;

    const uint32_t aoff = (uint32_t)((r0 + (lane & 15)) * 272 + ((lane >> 4) & 1) * 16);
    const uint32_t boff = (uint32_t)((cg * 64 + (lane & 7) + ((lane >> 4) & 1) * 8) * 272 + ((lane >> 3) & 1) * 16);

    CP_WAIT(0);
    __syncthreads();

    float sc[8][4];
    #pragma unroll
    for (int kc = 0; kc < 8; kc++) {
        uint32_t a0[4], a1[4];
        ldsm4(a0, sb + PX0 + aoff + kc * 32);
        ldsm4(a1, sb + PX1 + aoff + kc * 32);
        #pragma unroll
        for (int n2 = 0; n2 < 4; n2++) {
            uint32_t b[4];
            ldsm4(b, sb + PB0 + (uint32_t)(n2 * 16 * 272) + boff + kc * 32);
            if (kc == 0) {
                mma16816z(sc[2 * n2],     a0, b[0], b[1]);
                mma16816z(sc[2 * n2 + 1], a0, b[2], b[3]);
            } else {
                mma16816(sc[2 * n2],     a0, b[0], b[1]);
                mma16816(sc[2 * n2 + 1], a0, b[2], b[3]);
            }
            mma16816(sc[2 * n2],     a1, b[0], b[1]);
            mma16816(sc[2 * n2 + 1], a1, b[2], b[3]);
            uint32_t b1[4];
            ldsm4(b1, sb + PB1 + (uint32_t)(n2 * 16 * 272) + boff + kc * 32);
            mma16816(sc[2 * n2],     a0, b1[0], b1[1]);
            mma16816(sc[2 * n2 + 1], a0, b1[2], b1[3]);
            mma16816(sc[2 * n2],     a1, b1[0], b1[1]);
            mma16816(sc[2 * n2 + 1], a1, b1[2], b1[3]);
        }
    }

    #pragma unroll
    for (int nt = 0; nt < 8; nt++) {
        int col = cg * 64 + nt * 8 + qc;
        *reinterpret_cast<float2*>(g_m1 + (size_t)gr0 * CC + col) = make_float2(sc[nt][0], sc[nt][1]);
        *reinterpret_cast<float2*>(g_m1 + (size_t)gr1 * CC + col) = make_float2(sc[nt][2], sc[nt][3]);
    }
}

// ---------------- K7: GCN layer-1 gather + relu ----------------
__global__ __launch_bounds__(128) void gather1(const float* __restrict__ b1)
{
    int node = blockIdx.x;
    int c    = threadIdx.x;
    float s = g_m1[node * CC + c];
    #pragma unroll
    for (int t = 0; t < KNBR; t++) {
        int nb = g_idx[node * KNBR + t];
        s += g_m1[nb * CC + c];
    }
    g_h1[node * CC + c] = fmaxf(s * 0.125f + b1[c], 0.f);
}

// ---------------- K8: m2 = h1 @ W2 ----------------
__global__ __launch_bounds__(256) void m2_kernel(const float* __restrict__ W2)
{
    int row  = blockIdx.x * 8 + (threadIdx.x >> 5);
    int lane = threadIdx.x & 31;
    float s = 0.f;
    for (int c = lane; c < CC; c += 32) s += g_h1[row * CC + c] * W2[c];
    s += __shfl_xor_sync(0xffffffffu, s, 16);
    s += __shfl_xor_sync(0xffffffffu, s, 8);
    s += __shfl_xor_sync(0xffffffffu, s, 4);
    s += __shfl_xor_sync(0xffffffffu, s, 2);
    s += __shfl_xor_sync(0xffffffffu, s, 1);
    if (lane == 0) g_m2[row] = s;
}

// ---------------- K9: GCN layer-2 gather -> output ----------------
__global__ __launch_bounds__(256) void out_kernel(const float* __restrict__ b2,
                                                  float* __restrict__ out)
{
    int n = blockIdx.x * 256 + threadIdx.x;
    float s = g_m2[n];
    #pragma unroll
    for (int t = 0; t < KNBR; t++) s += g_m2[g_idx[n * KNBR + t]];
    out[n] = s * 0.125f + b2[0];
}

// ---------------- launch ----------------
extern "C" void kernel_launch(void* const* d_in, const int* in_sizes, int n_in,
                              void* d_out, int out_size)
{
    const float* x   = (const float*)d_in[0];
    const float* Wq  = (const float*)d_in[1];
    const float* bq  = (const float*)d_in[2];
    const float* Wk  = (const float*)d_in[3];
    const float* bk  = (const float*)d_in[4];
    const float* Wv  = (const float*)d_in[5];
    const float* bv  = (const float*)d_in[6];
    const float* Wsk = (const float*)d_in[7];
    const float* bsk = (const float*)d_in[8];
    const float* W1  = (const float*)d_in[9];
    const float* b1  = (const float*)d_in[10];
    const float* W2  = (const float*)d_in[11];
    const float* b2  = (const float*)d_in[12];
    float* out = (float*)d_out;

    cudaFuncSetAttribute(projqkv_mma_kernel, cudaFuncAttributeMaxDynamicSharedMemorySize, PROJ_SMEM);
    cudaFuncSetAttribute(attn_mma_kernel, cudaFuncAttributeMaxDynamicSharedMemorySize, ATTN_SMEM);
    cudaFuncSetAttribute(knn_mma_kernel,  cudaFuncAttributeMaxDynamicSharedMemorySize, KNN_SMEM);
    cudaFuncSetAttribute(gcn1_mma_kernel, cudaFuncAttributeMaxDynamicSharedMemorySize, PROJ_SMEM);

    split_w_kernel<<<dim3(64, 4), 256>>>(Wq, Wk, Wv, W1);
    skip_kernel<<<NN / 32, 256>>>(x, Wsk, bsk);
    projqkv_mma_kernel<<<NN / 64, 256, PROJ_SMEM>>>(x, bq, bk, bv);
    attn_mma_kernel<<<dim3(NN / 128, 2), 256, ATTN_SMEM>>>();
    combine_norm_kernel<<<NN / 8, 256>>>();
    knn_mma_kernel<<<dim3(NN / 128, 4), 256, KNN_SMEM>>>();
    knn_rescore_kernel<<<NN / 8, 256>>>();
    gcn1_mma_kernel<<<NN / 64, 256, PROJ_SMEM>>>();
    gather1<<<NN, CC>>>(b1);
    m2_kernel<<<NN / 8, 256>>>(W2);
    out_kernel<<<NN / 256, 256>>>(b2, out);
}